// round 1
// baseline (speedup 1.0000x reference)
#include <cuda_runtime.h>
#include <cuda_bf16.h>
#include <cstdint>

#define N_NODES 50000
#define N_EDGES 800000
#define NPOOL   25000
#define DIM     128
#define HID     256
#define NGRAPH  64

// ---------------- scratch (static __device__, no allocation) ----------------
__device__ float g_h0 [N_NODES * DIM];   // MLP0 output
__device__ float g_a0 [N_NODES * DIM];   // layer0 scatter accum -> h (in place)
__device__ float g_t1 [N_NODES * DIM];   // GEMM intermediate (also NPOOL*HID view)
__device__ float g_xp [NPOOL * DIM];     // pooled features
__device__ float g_h1m[NPOOL * DIM];     // MLP1 output
__device__ float g_a1 [NPOOL * DIM];     // layer1 scatter accum
__device__ float g_w0 [N_EDGES];
__device__ float g_w1 [N_EDGES];         // masked (0 for intra-cluster edges)
__device__ float g_deg0[N_NODES];
__device__ float g_deg1[NPOOL];
__device__ float g_dis0[N_NODES];
__device__ float g_dis1[NPOOL];
__device__ unsigned g_gmax[NGRAPH * DIM];

// ---------------- helpers ----------------
__device__ __forceinline__ unsigned encf(float f) {
    unsigned u = __float_as_uint(f);
    return (u & 0x80000000u) ? ~u : (u | 0x80000000u);
}
__device__ __forceinline__ float decf(unsigned k) {
    return (k & 0x80000000u) ? __uint_as_float(k & 0x7FFFFFFFu) : __uint_as_float(~k);
}
__device__ __forceinline__ float leaky(float v) { return v > 0.f ? v : 0.01f * v; }

// ---------------- zero scratch ----------------
__global__ void zero_kernel() {
    int i = blockIdx.x * blockDim.x + threadIdx.x;
    int stride = gridDim.x * blockDim.x;
    float4 z = make_float4(0.f, 0.f, 0.f, 0.f);
    float4* a0 = (float4*)g_a0;
    for (int k = i; k < N_NODES * DIM / 4; k += stride) a0[k] = z;
    float4* a1 = (float4*)g_a1;
    for (int k = i; k < NPOOL * DIM / 4; k += stride) a1[k] = z;
    for (int k = i; k < N_NODES; k += stride) g_deg0[k] = 0.f;
    for (int k = i; k < NPOOL; k += stride) g_deg1[k] = 0.f;
    for (int k = i; k < NGRAPH * DIM; k += stride) g_gmax[k] = 0u;  // enc(-FLT_MAX) lower bound
}

// ---------------- per-edge: weights + degrees ----------------
__global__ void edge_kernel(const int* __restrict__ ei, const float* __restrict__ ea,
                            const int* __restrict__ cluster,
                            const float* __restrict__ We0, const float* __restrict__ be0,
                            const float* __restrict__ We1, const float* __restrict__ be1) {
    __shared__ float sW0[12], sW1[12], sb0, sb1;
    int t = threadIdx.x;
    if (t < 12) sW0[t] = We0[t];
    else if (t < 24) sW1[t - 12] = We1[t - 12];
    if (t == 24) sb0 = be0[0];
    if (t == 25) sb1 = be1[0];
    __syncthreads();

    int e = blockIdx.x * blockDim.x + t;
    if (e >= N_EDGES) return;
    const float* a = ea + (size_t)e * 12;
    float w0 = sb0, w1 = sb1;
#pragma unroll
    for (int k = 0; k < 12; k++) { float av = a[k]; w0 += av * sW0[k]; w1 += av * sW1[k]; }
    int r = ei[e];
    int c = ei[N_EDGES + e];
    atomicAdd(&g_deg0[r], 1.0f);
    int rp = cluster[r], cp = cluster[c];
    bool m1 = (rp != cp);
    if (m1) atomicAdd(&g_deg1[rp], 1.0f);
    g_w0[e] = w0;
    g_w1[e] = m1 ? w1 : 0.f;
}

__global__ void dis_kernel() {
    int i = blockIdx.x * blockDim.x + threadIdx.x;
    if (i < N_NODES) g_dis0[i] = rsqrtf(g_deg0[i] + 1.0f);
    if (i < NPOOL)   g_dis1[i] = rsqrtf(g_deg1[i] + 1.0f);
}

// ---------------- SGEMM: C = act( A @ (W .* colscale) + (b*s+t) ) ----------------
// A: [rows,K] rm, W: [K,M] rm. BM=BN=128, BK=16, 256 thr, 8x8 per thread.
__global__ __launch_bounds__(256) void sgemm_kernel(
    const float* __restrict__ A, const float* __restrict__ W,
    const float* __restrict__ colscale,
    const float* __restrict__ bptr, const float* __restrict__ sptr, const float* __restrict__ tptr,
    float* __restrict__ C, int nrows, int K, int M, int act) {
    __shared__ float As[16][132];
    __shared__ float Bs[16][128];
    int row0 = blockIdx.x * 128;
    int col0 = blockIdx.y * 128;
    int tid = threadIdx.x;
    int tx = tid & 15, ty = tid >> 4;
    float acc[8][8];
#pragma unroll
    for (int i = 0; i < 8; i++)
#pragma unroll
        for (int j = 0; j < 8; j++) acc[i][j] = 0.f;

    for (int kk = 0; kk < K; kk += 16) {
        // A tile 128x16, transposed into As[k][m]
#pragma unroll
        for (int l = 0; l < 2; l++) {
            int f = tid + l * 256;       // 0..511 float4 slots
            int ar = f >> 2;             // 0..127
            int ak = (f & 3) * 4;        // 0,4,8,12
            int grow = row0 + ar;
            float4 v = make_float4(0.f, 0.f, 0.f, 0.f);
            if (grow < nrows) v = *(const float4*)&A[(size_t)grow * K + kk + ak];
            As[ak + 0][ar] = v.x; As[ak + 1][ar] = v.y;
            As[ak + 2][ar] = v.z; As[ak + 3][ar] = v.w;
        }
        // B tile 16x128
#pragma unroll
        for (int l = 0; l < 2; l++) {
            int f = tid + l * 256;
            int bk = f >> 5;             // 0..15
            int bm = (f & 31) * 4;
            float4 v = *(const float4*)&W[(size_t)(kk + bk) * M + col0 + bm];
            if (colscale) {
                v.x *= colscale[col0 + bm + 0]; v.y *= colscale[col0 + bm + 1];
                v.z *= colscale[col0 + bm + 2]; v.w *= colscale[col0 + bm + 3];
            }
            *(float4*)&Bs[bk][bm] = v;
        }
        __syncthreads();
#pragma unroll
        for (int k = 0; k < 16; k++) {
            float a[8], b[8];
            *(float4*)&a[0] = *(const float4*)&As[k][ty * 8];
            *(float4*)&a[4] = *(const float4*)&As[k][ty * 8 + 4];
            *(float4*)&b[0] = *(const float4*)&Bs[k][tx * 8];
            *(float4*)&b[4] = *(const float4*)&Bs[k][tx * 8 + 4];
#pragma unroll
            for (int i = 0; i < 8; i++)
#pragma unroll
                for (int j = 0; j < 8; j++) acc[i][j] += a[i] * b[j];
        }
        __syncthreads();
    }
    // epilogue
#pragma unroll
    for (int i = 0; i < 8; i++) {
        int r = row0 + ty * 8 + i;
        if (r >= nrows) break;
#pragma unroll
        for (int jj = 0; jj < 2; jj++) {
            float tmp[4];
#pragma unroll
            for (int j = 0; j < 4; j++) {
                int m = col0 + tx * 8 + jj * 4 + j;
                float bias = bptr ? bptr[m] : 0.f;
                if (sptr) bias = bias * sptr[m] + tptr[m];
                float u = acc[i][jj * 4 + j] + bias;
                if (act) u = leaky(u);
                tmp[j] = u;
            }
            *(float4*)&C[(size_t)r * M + col0 + tx * 8 + jj * 4] =
                make_float4(tmp[0], tmp[1], tmp[2], tmp[3]);
        }
    }
}

// ---------------- scatter: one warp per edge, red.v4.f32 ----------------
__global__ __launch_bounds__(256) void scatter0_kernel(const int* __restrict__ ei) {
    int e = blockIdx.x * 8 + (threadIdx.x >> 5);
    if (e >= N_EDGES) return;
    int lane = threadIdx.x & 31;
    int r = __ldg(&ei[e]);
    int c = __ldg(&ei[N_EDGES + e]);
    float coef = g_dis0[r] * g_dis0[c] * g_w0[e];
    float4 v = *(const float4*)&g_h0[(size_t)r * DIM + lane * 4];
    float4 o = make_float4(v.x * coef, v.y * coef, v.z * coef, v.w * coef);
    float* p = &g_a0[(size_t)c * DIM + lane * 4];
    asm volatile("red.global.add.v4.f32 [%0], {%1,%2,%3,%4};"
                 :: "l"(p), "f"(o.x), "f"(o.y), "f"(o.z), "f"(o.w) : "memory");
}

__global__ __launch_bounds__(256) void scatter1_kernel(const int* __restrict__ ei,
                                                       const int* __restrict__ cluster) {
    int e = blockIdx.x * 8 + (threadIdx.x >> 5);
    if (e >= N_EDGES) return;
    float w = g_w1[e];
    if (w == 0.f) return;          // masked (intra-cluster) or exactly-zero contribution
    int lane = threadIdx.x & 31;
    int r = __ldg(&ei[e]);
    int c = __ldg(&ei[N_EDGES + e]);
    int rp = __ldg(&cluster[r]);
    int cp = __ldg(&cluster[c]);
    float coef = g_dis1[rp] * g_dis1[cp] * w;
    float4 v = *(const float4*)&g_h1m[(size_t)rp * DIM + lane * 4];
    float4 o = make_float4(v.x * coef, v.y * coef, v.z * coef, v.w * coef);
    float* p = &g_a1[(size_t)cp * DIM + lane * 4];
    asm volatile("red.global.add.v4.f32 [%0], {%1,%2,%3,%4};"
                 :: "l"(p), "f"(o.x), "f"(o.y), "f"(o.z), "f"(o.w) : "memory");
}

// ---------------- post layer0: h = leaky(a0 + dis^2*wself*h0 + origin), in place ----------------
__global__ void post0_kernel(const float* __restrict__ origin,
                             const float* __restrict__ We, const float* __restrict__ be) {
    __shared__ float swself;
    if (threadIdx.x == 0) {
        float t = be[0];
        for (int k = 0; k < 12; k++) t += We[k];
        swself = t;
    }
    __syncthreads();
    int idx = blockIdx.x * blockDim.x + threadIdx.x;   // float4 index
    if (idx >= N_NODES * (DIM / 4)) return;
    int node = idx >> 5;
    float ds = g_dis0[node];
    float sc = ds * ds * swself;
    float4 a  = ((const float4*)g_a0)[idx];
    float4 h  = ((const float4*)g_h0)[idx];
    float4 og = ((const float4*)origin)[idx];
    float4 o;
    o.x = leaky(a.x + sc * h.x + og.x);
    o.y = leaky(a.y + sc * h.y + og.y);
    o.z = leaky(a.z + sc * h.z + og.z);
    o.w = leaky(a.w + sc * h.w + og.w);
    ((float4*)g_a0)[idx] = o;
}

// ---------------- graclus pool: xp[j] = max(h[2j], h[2j+1]) ----------------
__global__ void pool_kernel() {
    int idx = blockIdx.x * blockDim.x + threadIdx.x;   // float4 index into xp
    if (idx >= NPOOL * (DIM / 4)) return;
    int j = idx >> 5;
    int d = idx & 31;
    float4 a = ((const float4*)g_a0)[(size_t)(2 * j) * 32 + d];
    float4 b = ((const float4*)g_a0)[(size_t)(2 * j + 1) * 32 + d];
    float4 o;
    o.x = fmaxf(a.x, b.x); o.y = fmaxf(a.y, b.y);
    o.z = fmaxf(a.z, b.z); o.w = fmaxf(a.w, b.w);
    ((float4*)g_xp)[idx] = o;
}

// ---------------- post layer1 + global max pool (warp per pooled node) ----------------
__global__ __launch_bounds__(256) void post1_gmax_kernel(const int* __restrict__ batch_p,
                                                         const float* __restrict__ We,
                                                         const float* __restrict__ be) {
    __shared__ float swself;
    if (threadIdx.x == 0) {
        float t = be[0];
        for (int k = 0; k < 12; k++) t += We[k];
        swself = t;
    }
    __syncthreads();
    int j = blockIdx.x * 8 + (threadIdx.x >> 5);
    if (j >= NPOOL) return;
    int lane = threadIdx.x & 31;
    float ds = g_dis1[j];
    float sc = ds * ds * swself;
    float4 a  = ((const float4*)g_a1)[(size_t)j * 32 + lane];
    float4 hm = ((const float4*)g_h1m)[(size_t)j * 32 + lane];
    float v0 = leaky(a.x + sc * hm.x);
    float v1 = leaky(a.y + sc * hm.y);
    float v2 = leaky(a.z + sc * hm.z);
    float v3 = leaky(a.w + sc * hm.w);
    int b = __ldg(&batch_p[j]);
    unsigned* gp = &g_gmax[b * DIM + lane * 4];
    atomicMax(&gp[0], encf(v0));
    atomicMax(&gp[1], encf(v1));
    atomicMax(&gp[2], encf(v2));
    atomicMax(&gp[3], encf(v3));
}

// ---------------- head MLP: [G,128] -> [G,64] -> [G,1] ----------------
__global__ void head_kernel(const float* __restrict__ W1, const float* __restrict__ b1,
                            const float* __restrict__ s, const float* __restrict__ t,
                            const float* __restrict__ W2, const float* __restrict__ b2,
                            float* __restrict__ out) {
    __shared__ float grow[128];
    __shared__ float red[64];
    int r = blockIdx.x;
    int h = threadIdx.x;  // 64 threads
    grow[h]      = decf(g_gmax[r * DIM + h]);
    grow[h + 64] = decf(g_gmax[r * DIM + h + 64]);
    __syncthreads();
    float acc = 0.f;
#pragma unroll 4
    for (int k = 0; k < 128; k++) acc += grow[k] * W1[k * 64 + h];
    float v = (acc + b1[h]) * s[h] + t[h];
    v = leaky(v);
    red[h] = v * W2[h];
    __syncthreads();
    if (h == 0) {
        float total = b2[0];
        for (int k = 0; k < 64; k++) total += red[k];
        out[r] = total;
    }
}

// ---------------- launch ----------------
extern "C" void kernel_launch(void* const* d_in, const int* in_sizes, int n_in,
                              void* d_out, int out_size) {
    const float* x = (const float*)d_in[0];
    const float* origin;
    const float* ea;
    const int* ei;
    if (in_sizes[1] == N_NODES * DIM) {        // dict order: x, origin, edge_attr, edge_index
        origin = (const float*)d_in[1];
        ea     = (const float*)d_in[2];
        ei     = (const int*)d_in[3];
    } else {                                    // signature order: x, edge_index, edge_attr, origin
        ei     = (const int*)d_in[1];
        ea     = (const float*)d_in[2];
        origin = (const float*)d_in[3];
    }
    const int* cluster = (const int*)d_in[4];
    const int* batch_p = (const int*)d_in[5];
    const float* l0_W1 = (const float*)d_in[6];
    const float* l0_b1 = (const float*)d_in[7];
    const float* l0_s  = (const float*)d_in[8];
    const float* l0_t  = (const float*)d_in[9];
    const float* l0_W2 = (const float*)d_in[10];
    const float* l0_b2 = (const float*)d_in[11];
    const float* l0_We = (const float*)d_in[12];
    const float* l0_be = (const float*)d_in[13];
    const float* l1_W1 = (const float*)d_in[14];
    const float* l1_b1 = (const float*)d_in[15];
    const float* l1_s  = (const float*)d_in[16];
    const float* l1_t  = (const float*)d_in[17];
    const float* l1_W2 = (const float*)d_in[18];
    const float* l1_b2 = (const float*)d_in[19];
    const float* l1_We = (const float*)d_in[20];
    const float* l1_be = (const float*)d_in[21];
    const float* hd_W1 = (const float*)d_in[22];
    const float* hd_b1 = (const float*)d_in[23];
    const float* hd_s  = (const float*)d_in[24];
    const float* hd_t  = (const float*)d_in[25];
    const float* hd_W2 = (const float*)d_in[26];
    const float* hd_b2 = (const float*)d_in[27];
    float* out = (float*)d_out;

    float *p_h0, *p_t1, *p_xp, *p_h1m;
    cudaGetSymbolAddress((void**)&p_h0,  g_h0);
    cudaGetSymbolAddress((void**)&p_t1,  g_t1);
    cudaGetSymbolAddress((void**)&p_xp,  g_xp);
    cudaGetSymbolAddress((void**)&p_h1m, g_h1m);

    zero_kernel<<<2048, 256>>>();
    edge_kernel<<<(N_EDGES + 255) / 256, 256>>>(ei, ea, cluster, l0_We, l0_be, l1_We, l1_be);
    dis_kernel<<<(N_NODES + 255) / 256, 256>>>();

    // MLP0: t1 = leaky((x@W1)*s + b1*s + t);  h0 = t1@W2 + b2
    sgemm_kernel<<<dim3((N_NODES + 127) / 128, 1), 256>>>(
        x, l0_W1, l0_s, l0_b1, l0_s, l0_t, p_t1, N_NODES, 128, 128, 1);
    sgemm_kernel<<<dim3((N_NODES + 127) / 128, 1), 256>>>(
        p_t1, l0_W2, nullptr, l0_b2, nullptr, nullptr, p_h0, N_NODES, 128, 128, 0);

    scatter0_kernel<<<(N_EDGES + 7) / 8, 256>>>(ei);
    post0_kernel<<<(N_NODES * 32 + 255) / 256, 256>>>(origin, l0_We, l0_be);
    pool_kernel<<<(NPOOL * 32 + 255) / 256, 256>>>();

    // MLP1: t1 = leaky((xp@W1)*s + b1*s + t) [NPOOL,256];  h1m = t1@W2 + b2
    sgemm_kernel<<<dim3((NPOOL + 127) / 128, 2), 256>>>(
        p_xp, l1_W1, l1_s, l1_b1, l1_s, l1_t, p_t1, NPOOL, 128, 256, 1);
    sgemm_kernel<<<dim3((NPOOL + 127) / 128, 1), 256>>>(
        p_t1, l1_W2, nullptr, l1_b2, nullptr, nullptr, p_h1m, NPOOL, 256, 128, 0);

    scatter1_kernel<<<(N_EDGES + 7) / 8, 256>>>(ei, cluster);
    post1_gmax_kernel<<<(NPOOL + 7) / 8, 256>>>(batch_p, l1_We, l1_be);
    head_kernel<<<NGRAPH, 64>>>(hd_W1, hd_b1, hd_s, hd_t, hd_W2, hd_b2, out);
}

// round 3
// speedup vs baseline: 1.1234x; 1.1234x over previous
#include <cuda_runtime.h>
#include <cuda_bf16.h>
#include <cstdint>

#define N_NODES 50000
#define N_EDGES 800000
#define NPOOL   25000
#define DIM     128
#define HID     256
#define NGRAPH  64

// ---------------- scratch (static __device__, no allocation) ----------------
__device__ float g_h0 [N_NODES * DIM];   // MLP0 output
__device__ float g_a0 [N_NODES * DIM];   // layer0 scatter accum
__device__ float g_t1 [N_NODES * DIM];   // GEMM intermediate (also NPOOL*HID view)
__device__ float g_xp [NPOOL * DIM];     // pooled features
__device__ float g_h1m[NPOOL * DIM];     // MLP1 output
__device__ float g_a1 [NPOOL * DIM];     // layer1 scatter accum
__device__ float g_w0 [N_EDGES];
__device__ float g_w1 [N_EDGES];         // masked (0 for intra-cluster edges)
__device__ float g_deg0[N_NODES];
__device__ float g_deg1[NPOOL];
__device__ float g_dis0[N_NODES];
__device__ float g_dis1[NPOOL];
__device__ unsigned g_gmax[NGRAPH * DIM];

// ---------------- helpers ----------------
__device__ __forceinline__ unsigned encf(float f) {
    unsigned u = __float_as_uint(f);
    return (u & 0x80000000u) ? ~u : (u | 0x80000000u);
}
__device__ __forceinline__ float decf(unsigned k) {
    return (k & 0x80000000u) ? __uint_as_float(k & 0x7FFFFFFFu) : __uint_as_float(~k);
}
__device__ __forceinline__ float leaky(float v) { return v > 0.f ? v : 0.01f * v; }

// ---------------- zero scratch ----------------
__global__ void zero_kernel() {
    int i = blockIdx.x * blockDim.x + threadIdx.x;
    int stride = gridDim.x * blockDim.x;
    float4 z = make_float4(0.f, 0.f, 0.f, 0.f);
    float4* a0 = (float4*)g_a0;
    for (int k = i; k < N_NODES * DIM / 4; k += stride) a0[k] = z;
    float4* a1 = (float4*)g_a1;
    for (int k = i; k < NPOOL * DIM / 4; k += stride) a1[k] = z;
    for (int k = i; k < N_NODES; k += stride) g_deg0[k] = 0.f;
    for (int k = i; k < NPOOL; k += stride) g_deg1[k] = 0.f;
    for (int k = i; k < NGRAPH * DIM; k += stride) g_gmax[k] = 0u;  // enc lower bound
}

// ---------------- per-edge: weights + degrees ----------------
__global__ void edge_kernel(const int* __restrict__ ei, const float* __restrict__ ea,
                            const int* __restrict__ cluster,
                            const float* __restrict__ We0, const float* __restrict__ be0,
                            const float* __restrict__ We1, const float* __restrict__ be1) {
    __shared__ float sW0[12], sW1[12], sb0, sb1;
    int t = threadIdx.x;
    if (t < 12) sW0[t] = We0[t];
    else if (t < 24) sW1[t - 12] = We1[t - 12];
    if (t == 24) sb0 = be0[0];
    if (t == 25) sb1 = be1[0];
    __syncthreads();

    int e = blockIdx.x * blockDim.x + t;
    if (e >= N_EDGES) return;
    const float* a = ea + (size_t)e * 12;
    float w0 = sb0, w1 = sb1;
#pragma unroll
    for (int k = 0; k < 12; k++) { float av = a[k]; w0 += av * sW0[k]; w1 += av * sW1[k]; }
    int r = ei[e];
    int c = ei[N_EDGES + e];
    atomicAdd(&g_deg0[r], 1.0f);
    int rp = cluster[r], cp = cluster[c];
    bool m1 = (rp != cp);
    if (m1) atomicAdd(&g_deg1[rp], 1.0f);
    g_w0[e] = w0;
    g_w1[e] = m1 ? w1 : 0.f;
}

__global__ void dis_kernel() {
    int i = blockIdx.x * blockDim.x + threadIdx.x;
    if (i < N_NODES) g_dis0[i] = rsqrtf(g_deg0[i] + 1.0f);
    if (i < NPOOL)   g_dis1[i] = rsqrtf(g_deg1[i] + 1.0f);
}

// ---------------- bf16 3-term split-precision tensor-core GEMM ----------------
// x = hi + lo (hi = bf16(x), lo = bf16(x-hi)); A@B = Ah@Bh + Ah@Bl + Al@Bh  (fp32 acc)
// C[r,m] = act( (A@W)[r,m]*s[m] + (b[m]*s[m]+t[m]) )
// A: [rows,K] rm fp32, W: [K,M] rm fp32. BM=BN=128, BK=32.
// 8 warps 4(m)x2(n); warp tile 32x64; mma m16n8k16 bf16.
#define KP 34   // smem k pitch (bf16 elems)
__global__ __launch_bounds__(256) void bf16x3_gemm_kernel(
    const float* __restrict__ A, const float* __restrict__ W,
    const float* __restrict__ bptr, const float* __restrict__ sptr, const float* __restrict__ tptr,
    float* __restrict__ C, int nrows, int K, int M, int act) {
    __shared__ __nv_bfloat16 Ah[128][KP];   // [m][k]
    __shared__ __nv_bfloat16 Al[128][KP];
    __shared__ __nv_bfloat16 Bh[128][KP];   // [n][k]
    __shared__ __nv_bfloat16 Bl[128][KP];
    int row0 = blockIdx.x * 128;
    int col0 = blockIdx.y * 128;
    int tid = threadIdx.x;
    int wid = tid >> 5, lane = tid & 31;
    int wm = wid & 3;          // warp row block (32 rows)
    int wn = wid >> 2;         // warp col block (64 cols)
    int gid = lane >> 2, tig = lane & 3;

    float acc[2][8][4];
#pragma unroll
    for (int i = 0; i < 2; i++)
#pragma unroll
        for (int j = 0; j < 8; j++)
#pragma unroll
            for (int q = 0; q < 4; q++) acc[i][j][q] = 0.f;

    for (int kk = 0; kk < K; kk += 32) {
        // A tile: 128 rows x 32 k -> Ah/Al[m][k]
#pragma unroll
        for (int l = 0; l < 4; l++) {
            int f = tid + l * 256;          // 1024 float4 slots
            int ar = f >> 3;                // row 0..127
            int ak = (f & 7) * 4;           // k 0..28
            int grow = row0 + ar;
            float4 v = make_float4(0.f, 0.f, 0.f, 0.f);
            if (grow < nrows) v = *(const float4*)&A[(size_t)grow * K + kk + ak];
            float vv[4] = {v.x, v.y, v.z, v.w};
#pragma unroll
            for (int c = 0; c < 4; c++) {
                __nv_bfloat16 h = __float2bfloat16_rn(vv[c]);
                Ah[ar][ak + c] = h;
                Al[ar][ak + c] = __float2bfloat16_rn(vv[c] - __bfloat162float(h));
            }
        }
        // B tile: 32 k x 128 n -> Bh/Bl[n][k] (transposed)
#pragma unroll
        for (int l = 0; l < 4; l++) {
            int f = tid + l * 256;
            int bk = f >> 5;                // k 0..31
            int bn = (f & 31) * 4;          // n 0..124
            float4 v = *(const float4*)&W[(size_t)(kk + bk) * M + col0 + bn];
            float vv[4] = {v.x, v.y, v.z, v.w};
#pragma unroll
            for (int c = 0; c < 4; c++) {
                __nv_bfloat16 h = __float2bfloat16_rn(vv[c]);
                Bh[bn + c][bk] = h;
                Bl[bn + c][bk] = __float2bfloat16_rn(vv[c] - __bfloat162float(h));
            }
        }
        __syncthreads();
#pragma unroll
        for (int ks = 0; ks < 2; ks++) {
            int k0 = ks * 16;
            int kf = k0 + 2 * tig;          // fragment k offset (even -> 4B aligned)
            uint32_t ah[2][4], al[2][4];
#pragma unroll
            for (int i = 0; i < 2; i++) {
                int mrow = wm * 32 + i * 16 + gid;
                ah[i][0] = *(const uint32_t*)&Ah[mrow][kf];
                ah[i][1] = *(const uint32_t*)&Ah[mrow + 8][kf];
                ah[i][2] = *(const uint32_t*)&Ah[mrow][kf + 8];
                ah[i][3] = *(const uint32_t*)&Ah[mrow + 8][kf + 8];
                al[i][0] = *(const uint32_t*)&Al[mrow][kf];
                al[i][1] = *(const uint32_t*)&Al[mrow + 8][kf];
                al[i][2] = *(const uint32_t*)&Al[mrow][kf + 8];
                al[i][3] = *(const uint32_t*)&Al[mrow + 8][kf + 8];
            }
#pragma unroll
            for (int j = 0; j < 8; j++) {
                int nb = wn * 64 + j * 8 + gid;
                uint32_t bh0 = *(const uint32_t*)&Bh[nb][kf];
                uint32_t bh1 = *(const uint32_t*)&Bh[nb][kf + 8];
                uint32_t bl0 = *(const uint32_t*)&Bl[nb][kf];
                uint32_t bl1 = *(const uint32_t*)&Bl[nb][kf + 8];
#pragma unroll
                for (int i = 0; i < 2; i++) {
                    asm volatile(
                        "mma.sync.aligned.m16n8k16.row.col.f32.bf16.bf16.f32 "
                        "{%0,%1,%2,%3},{%4,%5,%6,%7},{%8,%9},{%0,%1,%2,%3};"
                        : "+f"(acc[i][j][0]), "+f"(acc[i][j][1]),
                          "+f"(acc[i][j][2]), "+f"(acc[i][j][3])
                        : "r"(ah[i][0]), "r"(ah[i][1]), "r"(ah[i][2]), "r"(ah[i][3]),
                          "r"(bh0), "r"(bh1));
                    asm volatile(
                        "mma.sync.aligned.m16n8k16.row.col.f32.bf16.bf16.f32 "
                        "{%0,%1,%2,%3},{%4,%5,%6,%7},{%8,%9},{%0,%1,%2,%3};"
                        : "+f"(acc[i][j][0]), "+f"(acc[i][j][1]),
                          "+f"(acc[i][j][2]), "+f"(acc[i][j][3])
                        : "r"(ah[i][0]), "r"(ah[i][1]), "r"(ah[i][2]), "r"(ah[i][3]),
                          "r"(bl0), "r"(bl1));
                    asm volatile(
                        "mma.sync.aligned.m16n8k16.row.col.f32.bf16.bf16.f32 "
                        "{%0,%1,%2,%3},{%4,%5,%6,%7},{%8,%9},{%0,%1,%2,%3};"
                        : "+f"(acc[i][j][0]), "+f"(acc[i][j][1]),
                          "+f"(acc[i][j][2]), "+f"(acc[i][j][3])
                        : "r"(al[i][0]), "r"(al[i][1]), "r"(al[i][2]), "r"(al[i][3]),
                          "r"(bh0), "r"(bh1));
                }
            }
        }
        __syncthreads();
    }

    // epilogue: acc[i][j] = {(r,c),(r,c+1),(r+8,c),(r+8,c+1)}
    int rbase = row0 + wm * 32;
    int cbase = col0 + wn * 64;
#pragma unroll
    for (int j = 0; j < 8; j++) {
        int c0 = cbase + j * 8 + 2 * tig;
        float s0 = 1.f, s1 = 1.f, bb0 = 0.f, bb1 = 0.f;
        if (bptr) { bb0 = bptr[c0]; bb1 = bptr[c0 + 1]; }
        if (sptr) {
            s0 = sptr[c0]; s1 = sptr[c0 + 1];
            bb0 = bb0 * s0 + tptr[c0];
            bb1 = bb1 * s1 + tptr[c0 + 1];
        }
#pragma unroll
        for (int i = 0; i < 2; i++) {
            int r0 = rbase + i * 16 + gid;
#pragma unroll
            for (int h = 0; h < 2; h++) {
                int r = r0 + h * 8;
                if (r < nrows) {
                    float u0 = acc[i][j][h * 2 + 0] * s0 + bb0;
                    float u1 = acc[i][j][h * 2 + 1] * s1 + bb1;
                    if (act) { u0 = leaky(u0); u1 = leaky(u1); }
                    *(float2*)&C[(size_t)r * M + c0] = make_float2(u0, u1);
                }
            }
        }
    }
}

// ---------------- scatter: one warp per edge, red.v4.f32 ----------------
__global__ __launch_bounds__(256) void scatter0_kernel(const int* __restrict__ ei) {
    int e = blockIdx.x * 8 + (threadIdx.x >> 5);
    if (e >= N_EDGES) return;
    int lane = threadIdx.x & 31;
    int r = __ldg(&ei[e]);
    int c = __ldg(&ei[N_EDGES + e]);
    float coef = g_dis0[r] * g_dis0[c] * g_w0[e];
    float4 v = *(const float4*)&g_h0[(size_t)r * DIM + lane * 4];
    float4 o = make_float4(v.x * coef, v.y * coef, v.z * coef, v.w * coef);
    float* p = &g_a0[(size_t)c * DIM + lane * 4];
    asm volatile("red.global.add.v4.f32 [%0], {%1,%2,%3,%4};"
                 :: "l"(p), "f"(o.x), "f"(o.y), "f"(o.z), "f"(o.w) : "memory");
}

__global__ __launch_bounds__(256) void scatter1_kernel(const int* __restrict__ ei,
                                                       const int* __restrict__ cluster) {
    int e = blockIdx.x * 8 + (threadIdx.x >> 5);
    if (e >= N_EDGES) return;
    float w = g_w1[e];
    if (w == 0.f) return;          // masked (intra-cluster) or exactly-zero contribution
    int lane = threadIdx.x & 31;
    int r = __ldg(&ei[e]);
    int c = __ldg(&ei[N_EDGES + e]);
    int rp = __ldg(&cluster[r]);
    int cp = __ldg(&cluster[c]);
    float coef = g_dis1[rp] * g_dis1[cp] * w;
    float4 v = *(const float4*)&g_h1m[(size_t)rp * DIM + lane * 4];
    float4 o = make_float4(v.x * coef, v.y * coef, v.z * coef, v.w * coef);
    float* p = &g_a1[(size_t)cp * DIM + lane * 4];
    asm volatile("red.global.add.v4.f32 [%0], {%1,%2,%3,%4};"
                 :: "l"(p), "f"(o.x), "f"(o.y), "f"(o.z), "f"(o.w) : "memory");
}

// ---------------- fused post-layer0 + graclus pool ----------------
__global__ void post0_pool_kernel(const float* __restrict__ origin,
                                  const float* __restrict__ We, const float* __restrict__ be) {
    __shared__ float swself;
    if (threadIdx.x == 0) {
        float t = be[0];
        for (int k = 0; k < 12; k++) t += We[k];
        swself = t;
    }
    __syncthreads();
    int idx = blockIdx.x * blockDim.x + threadIdx.x;   // float4 index into xp
    if (idx >= NPOOL * (DIM / 4)) return;
    int j = idx >> 5;
    int d = idx & 31;
    float4 o;
    {
        int n = 2 * j;
        float ds = g_dis0[n];
        float sc = ds * ds * swself;
        float4 a  = ((const float4*)g_a0)[(size_t)n * 32 + d];
        float4 h  = ((const float4*)g_h0)[(size_t)n * 32 + d];
        float4 og = ((const float4*)origin)[(size_t)n * 32 + d];
        o.x = leaky(a.x + sc * h.x + og.x);
        o.y = leaky(a.y + sc * h.y + og.y);
        o.z = leaky(a.z + sc * h.z + og.z);
        o.w = leaky(a.w + sc * h.w + og.w);
    }
    {
        int n = 2 * j + 1;
        float ds = g_dis0[n];
        float sc = ds * ds * swself;
        float4 a  = ((const float4*)g_a0)[(size_t)n * 32 + d];
        float4 h  = ((const float4*)g_h0)[(size_t)n * 32 + d];
        float4 og = ((const float4*)origin)[(size_t)n * 32 + d];
        o.x = fmaxf(o.x, leaky(a.x + sc * h.x + og.x));
        o.y = fmaxf(o.y, leaky(a.y + sc * h.y + og.y));
        o.z = fmaxf(o.z, leaky(a.z + sc * h.z + og.z));
        o.w = fmaxf(o.w, leaky(a.w + sc * h.w + og.w));
    }
    ((float4*)g_xp)[idx] = o;
}

// ---------------- post layer1 + global max pool (warp per pooled node) ----------------
__global__ __launch_bounds__(256) void post1_gmax_kernel(const int* __restrict__ batch_p,
                                                         const float* __restrict__ We,
                                                         const float* __restrict__ be) {
    __shared__ float swself;
    if (threadIdx.x == 0) {
        float t = be[0];
        for (int k = 0; k < 12; k++) t += We[k];
        swself = t;
    }
    __syncthreads();
    int j = blockIdx.x * 8 + (threadIdx.x >> 5);
    if (j >= NPOOL) return;
    int lane = threadIdx.x & 31;
    float ds = g_dis1[j];
    float sc = ds * ds * swself;
    float4 a  = ((const float4*)g_a1)[(size_t)j * 32 + lane];
    float4 hm = ((const float4*)g_h1m)[(size_t)j * 32 + lane];
    float v0 = leaky(a.x + sc * hm.x);
    float v1 = leaky(a.y + sc * hm.y);
    float v2 = leaky(a.z + sc * hm.z);
    float v3 = leaky(a.w + sc * hm.w);
    int b = __ldg(&batch_p[j]);
    unsigned* gp = &g_gmax[b * DIM + lane * 4];
    atomicMax(&gp[0], encf(v0));
    atomicMax(&gp[1], encf(v1));
    atomicMax(&gp[2], encf(v2));
    atomicMax(&gp[3], encf(v3));
}

// ---------------- head MLP: [G,128] -> [G,64] -> [G,1] ----------------
__global__ void head_kernel(const float* __restrict__ W1, const float* __restrict__ b1,
                            const float* __restrict__ s, const float* __restrict__ t,
                            const float* __restrict__ W2, const float* __restrict__ b2,
                            float* __restrict__ out) {
    __shared__ float grow[128];
    __shared__ float red[64];
    int r = blockIdx.x;
    int h = threadIdx.x;  // 64 threads
    grow[h]      = decf(g_gmax[r * DIM + h]);
    grow[h + 64] = decf(g_gmax[r * DIM + h + 64]);
    __syncthreads();
    float acc = 0.f;
#pragma unroll 4
    for (int k = 0; k < 128; k++) acc += grow[k] * W1[k * 64 + h];
    float v = (acc + b1[h]) * s[h] + t[h];
    v = leaky(v);
    red[h] = v * W2[h];
    __syncthreads();
    if (h == 0) {
        float total = b2[0];
        for (int k = 0; k < 64; k++) total += red[k];
        out[r] = total;
    }
}

// ---------------- launch ----------------
extern "C" void kernel_launch(void* const* d_in, const int* in_sizes, int n_in,
                              void* d_out, int out_size) {
    const float* x = (const float*)d_in[0];
    const float* origin;
    const float* ea;
    const int* ei;
    if (in_sizes[1] == N_NODES * DIM) {        // dict order: x, origin, edge_attr, edge_index
        origin = (const float*)d_in[1];
        ea     = (const float*)d_in[2];
        ei     = (const int*)d_in[3];
    } else {                                    // signature order: x, edge_index, edge_attr, origin
        ei     = (const int*)d_in[1];
        ea     = (const float*)d_in[2];
        origin = (const float*)d_in[3];
    }
    const int* cluster = (const int*)d_in[4];
    const int* batch_p = (const int*)d_in[5];
    const float* l0_W1 = (const float*)d_in[6];
    const float* l0_b1 = (const float*)d_in[7];
    const float* l0_s  = (const float*)d_in[8];
    const float* l0_t  = (const float*)d_in[9];
    const float* l0_W2 = (const float*)d_in[10];
    const float* l0_b2 = (const float*)d_in[11];
    const float* l0_We = (const float*)d_in[12];
    const float* l0_be = (const float*)d_in[13];
    const float* l1_W1 = (const float*)d_in[14];
    const float* l1_b1 = (const float*)d_in[15];
    const float* l1_s  = (const float*)d_in[16];
    const float* l1_t  = (const float*)d_in[17];
    const float* l1_W2 = (const float*)d_in[18];
    const float* l1_b2 = (const float*)d_in[19];
    const float* l1_We = (const float*)d_in[20];
    const float* l1_be = (const float*)d_in[21];
    const float* hd_W1 = (const float*)d_in[22];
    const float* hd_b1 = (const float*)d_in[23];
    const float* hd_s  = (const float*)d_in[24];
    const float* hd_t  = (const float*)d_in[25];
    const float* hd_W2 = (const float*)d_in[26];
    const float* hd_b2 = (const float*)d_in[27];
    float* out = (float*)d_out;

    float *p_h0, *p_t1, *p_xp, *p_h1m;
    cudaGetSymbolAddress((void**)&p_h0,  g_h0);
    cudaGetSymbolAddress((void**)&p_t1,  g_t1);
    cudaGetSymbolAddress((void**)&p_xp,  g_xp);
    cudaGetSymbolAddress((void**)&p_h1m, g_h1m);

    zero_kernel<<<2048, 256>>>();
    edge_kernel<<<(N_EDGES + 255) / 256, 256>>>(ei, ea, cluster, l0_We, l0_be, l1_We, l1_be);
    dis_kernel<<<(N_NODES + 255) / 256, 256>>>();

    // MLP0: t1 = leaky((x@W1)*s + b1*s + t);  h0 = t1@W2 + b2
    bf16x3_gemm_kernel<<<dim3((N_NODES + 127) / 128, 1), 256>>>(
        x, l0_W1, l0_b1, l0_s, l0_t, p_t1, N_NODES, 128, 128, 1);
    bf16x3_gemm_kernel<<<dim3((N_NODES + 127) / 128, 1), 256>>>(
        p_t1, l0_W2, l0_b2, nullptr, nullptr, p_h0, N_NODES, 128, 128, 0);

    scatter0_kernel<<<(N_EDGES + 7) / 8, 256>>>(ei);
    post0_pool_kernel<<<(NPOOL * 32 + 255) / 256, 256>>>(origin, l0_We, l0_be);

    // MLP1: t1 = leaky((xp@W1)*s + b1*s + t) [NPOOL,256];  h1m = t1@W2 + b2
    bf16x3_gemm_kernel<<<dim3((NPOOL + 127) / 128, 2), 256>>>(
        p_xp, l1_W1, l1_b1, l1_s, l1_t, p_t1, NPOOL, 128, 256, 1);
    bf16x3_gemm_kernel<<<dim3((NPOOL + 127) / 128, 1), 256>>>(
        p_t1, l1_W2, l1_b2, nullptr, nullptr, p_h1m, NPOOL, 256, 128, 0);

    scatter1_kernel<<<(N_EDGES + 7) / 8, 256>>>(ei, cluster);
    post1_gmax_kernel<<<(NPOOL + 7) / 8, 256>>>(batch_p, l1_We, l1_be);
    head_kernel<<<NGRAPH, 64>>>(hd_W1, hd_b1, hd_s, hd_t, hd_W2, hd_b2, out);
}

// round 4
// speedup vs baseline: 1.3557x; 1.2068x over previous
#include <cuda_runtime.h>
#include <cuda_bf16.h>
#include <cstdint>

#define N_NODES 50000
#define N_EDGES 800000
#define NPOOL   25000
#define DIM     128
#define HID     256
#define NGRAPH  64

// ---------------- scratch (static __device__, no allocation) ----------------
__device__ float g_h0 [N_NODES * DIM];   // MLP0 output
__device__ float g_a0 [N_NODES * DIM];   // layer0 scatter accum
__device__ float g_t1 [N_NODES * DIM];   // GEMM intermediate (also NPOOL*HID view)
__device__ float g_xp [NPOOL * DIM];     // pooled features
__device__ float g_h1m[NPOOL * DIM];     // MLP1 output
__device__ float g_a1 [NPOOL * DIM];     // layer1 scatter accum
__device__ float g_w0 [N_EDGES];
__device__ float g_w1 [N_EDGES];         // masked (0 for intra-cluster edges)
__device__ float g_deg0[N_NODES];
__device__ float g_deg1[NPOOL];
__device__ float g_dis0[N_NODES];
__device__ float g_dis1[NPOOL];
__device__ unsigned g_gmax[NGRAPH * DIM];

// ---------------- helpers ----------------
__device__ __forceinline__ unsigned encf(float f) {
    unsigned u = __float_as_uint(f);
    return (u & 0x80000000u) ? ~u : (u | 0x80000000u);
}
__device__ __forceinline__ float decf(unsigned k) {
    return (k & 0x80000000u) ? __uint_as_float(k & 0x7FFFFFFFu) : __uint_as_float(~k);
}
__device__ __forceinline__ float leaky(float v) { return v > 0.f ? v : 0.01f * v; }

__device__ __forceinline__ void ldsm4(uint32_t& r0, uint32_t& r1, uint32_t& r2, uint32_t& r3,
                                      uint32_t addr) {
    asm volatile("ldmatrix.sync.aligned.m8n8.x4.shared.b16 {%0,%1,%2,%3}, [%4];"
                 : "=r"(r0), "=r"(r1), "=r"(r2), "=r"(r3) : "r"(addr));
}
__device__ __forceinline__ void ldsm4t(uint32_t& r0, uint32_t& r1, uint32_t& r2, uint32_t& r3,
                                       uint32_t addr) {
    asm volatile("ldmatrix.sync.aligned.m8n8.x4.trans.shared.b16 {%0,%1,%2,%3}, [%4];"
                 : "=r"(r0), "=r"(r1), "=r"(r2), "=r"(r3) : "r"(addr));
}

// ---------------- zero scratch ----------------
__global__ void zero_kernel() {
    int i = blockIdx.x * blockDim.x + threadIdx.x;
    int stride = gridDim.x * blockDim.x;
    float4 z = make_float4(0.f, 0.f, 0.f, 0.f);
    float4* a0 = (float4*)g_a0;
    for (int k = i; k < N_NODES * DIM / 4; k += stride) a0[k] = z;
    float4* a1 = (float4*)g_a1;
    for (int k = i; k < NPOOL * DIM / 4; k += stride) a1[k] = z;
    for (int k = i; k < N_NODES; k += stride) g_deg0[k] = 0.f;
    for (int k = i; k < NPOOL; k += stride) g_deg1[k] = 0.f;
    for (int k = i; k < NGRAPH * DIM; k += stride) g_gmax[k] = 0u;  // enc lower bound
}

// ---------------- per-edge: weights + degrees ----------------
__global__ void edge_kernel(const int* __restrict__ ei, const float* __restrict__ ea,
                            const int* __restrict__ cluster,
                            const float* __restrict__ We0, const float* __restrict__ be0,
                            const float* __restrict__ We1, const float* __restrict__ be1) {
    __shared__ float sW0[12], sW1[12], sb0, sb1;
    int t = threadIdx.x;
    if (t < 12) sW0[t] = We0[t];
    else if (t < 24) sW1[t - 12] = We1[t - 12];
    if (t == 24) sb0 = be0[0];
    if (t == 25) sb1 = be1[0];
    __syncthreads();

    int e = blockIdx.x * blockDim.x + t;
    if (e >= N_EDGES) return;
    const float* a = ea + (size_t)e * 12;
    float w0 = sb0, w1 = sb1;
#pragma unroll
    for (int k = 0; k < 12; k++) { float av = a[k]; w0 += av * sW0[k]; w1 += av * sW1[k]; }
    int r = ei[e];
    int c = ei[N_EDGES + e];
    atomicAdd(&g_deg0[r], 1.0f);
    int rp = cluster[r], cp = cluster[c];
    bool m1 = (rp != cp);
    if (m1) atomicAdd(&g_deg1[rp], 1.0f);
    g_w0[e] = w0;
    g_w1[e] = m1 ? w1 : 0.f;
}

__global__ void dis_kernel() {
    int i = blockIdx.x * blockDim.x + threadIdx.x;
    if (i < N_NODES) g_dis0[i] = rsqrtf(g_deg0[i] + 1.0f);
    if (i < NPOOL)   g_dis1[i] = rsqrtf(g_deg1[i] + 1.0f);
}

// ---------------- bf16 3-term split-precision tensor-core GEMM (ldmatrix) ----------------
// x = hi + lo; A@B = Ah@Bh + Ah@Bl + Al@Bh (fp32 acc).
// A: [rows,K] rm fp32, W: [K,M] rm fp32. BM=BN=128, BK=32.
// 8 warps 4(m)x2(n); warp tile 32x64; mma m16n8k16 bf16.
#define KP 40    // A smem k-pitch (bf16)  -> conflict-free ldmatrix
#define NP 136   // B smem n-pitch (bf16)  -> conflict-free ldmatrix.trans
__global__ __launch_bounds__(256, 2) void bf16x3_gemm_kernel(
    const float* __restrict__ A, const float* __restrict__ W,
    const float* __restrict__ bptr, const float* __restrict__ sptr, const float* __restrict__ tptr,
    float* __restrict__ C, int nrows, int K, int M, int act) {
    __shared__ __nv_bfloat16 Ah[128][KP];   // [m][k]
    __shared__ __nv_bfloat16 Al[128][KP];
    __shared__ __nv_bfloat16 Bh[32][NP];    // [k][n]
    __shared__ __nv_bfloat16 Bl[32][NP];
    int row0 = blockIdx.x * 128;
    int col0 = blockIdx.y * 128;
    int tid = threadIdx.x;
    int wid = tid >> 5, lane = tid & 31;
    int wm = wid & 3;          // warp row block (32 rows)
    int wn = wid >> 2;         // warp col block (64 cols)
    int gid = lane >> 2, tig = lane & 3;
    int sub = lane >> 3, lr = lane & 7;

    uint32_t baseAh = (uint32_t)__cvta_generic_to_shared(&Ah[0][0]);
    uint32_t baseAl = (uint32_t)__cvta_generic_to_shared(&Al[0][0]);
    uint32_t baseBh = (uint32_t)__cvta_generic_to_shared(&Bh[0][0]);
    uint32_t baseBl = (uint32_t)__cvta_generic_to_shared(&Bl[0][0]);
    // A ldmatrix (non-trans): blocks (m,k),(m+8,k),(m,k+8),(m+8,k+8)
    uint32_t offA = ((wm * 32 + (sub & 1) * 8 + lr) * KP + (sub >> 1) * 8) * 2;
    // B ldmatrix.trans on [k][n]: blocks (k,n),(k+8,n),(k,n+8),(k+8,n+8)
    uint32_t offB = (((sub & 1) * 8 + lr) * NP + wn * 64 + (sub >> 1) * 8) * 2;

    float acc[2][8][4];
#pragma unroll
    for (int i = 0; i < 2; i++)
#pragma unroll
        for (int j = 0; j < 8; j++)
#pragma unroll
            for (int q = 0; q < 4; q++) acc[i][j][q] = 0.f;

    for (int kk = 0; kk < K; kk += 32) {
        // A tile: 128 rows x 32 k -> Ah/Al[m][k]
#pragma unroll
        for (int l = 0; l < 4; l++) {
            int f = tid + l * 256;          // 1024 float4 slots
            int ar = f >> 3;                // row 0..127
            int ak = (f & 7) * 4;           // k 0..28
            int grow = row0 + ar;
            float4 v = make_float4(0.f, 0.f, 0.f, 0.f);
            if (grow < nrows) v = *(const float4*)&A[(size_t)grow * K + kk + ak];
            float vv[4] = {v.x, v.y, v.z, v.w};
            __nv_bfloat16 h0 = __float2bfloat16_rn(vv[0]);
            __nv_bfloat16 h1 = __float2bfloat16_rn(vv[1]);
            __nv_bfloat16 h2 = __float2bfloat16_rn(vv[2]);
            __nv_bfloat16 h3 = __float2bfloat16_rn(vv[3]);
            *(__nv_bfloat162*)&Ah[ar][ak]     = __nv_bfloat162(h0, h1);
            *(__nv_bfloat162*)&Ah[ar][ak + 2] = __nv_bfloat162(h2, h3);
            *(__nv_bfloat162*)&Al[ar][ak] = __nv_bfloat162(
                __float2bfloat16_rn(vv[0] - __bfloat162float(h0)),
                __float2bfloat16_rn(vv[1] - __bfloat162float(h1)));
            *(__nv_bfloat162*)&Al[ar][ak + 2] = __nv_bfloat162(
                __float2bfloat16_rn(vv[2] - __bfloat162float(h2)),
                __float2bfloat16_rn(vv[3] - __bfloat162float(h3)));
        }
        // B tile: 32 k x 128 n -> Bh/Bl[k][n] (no transpose)
#pragma unroll
        for (int l = 0; l < 4; l++) {
            int f = tid + l * 256;
            int bk = f >> 5;                // k 0..31
            int bn = (f & 31) * 4;          // n 0..124
            float4 v = *(const float4*)&W[(size_t)(kk + bk) * M + col0 + bn];
            float vv[4] = {v.x, v.y, v.z, v.w};
            __nv_bfloat16 h0 = __float2bfloat16_rn(vv[0]);
            __nv_bfloat16 h1 = __float2bfloat16_rn(vv[1]);
            __nv_bfloat16 h2 = __float2bfloat16_rn(vv[2]);
            __nv_bfloat16 h3 = __float2bfloat16_rn(vv[3]);
            *(__nv_bfloat162*)&Bh[bk][bn]     = __nv_bfloat162(h0, h1);
            *(__nv_bfloat162*)&Bh[bk][bn + 2] = __nv_bfloat162(h2, h3);
            *(__nv_bfloat162*)&Bl[bk][bn] = __nv_bfloat162(
                __float2bfloat16_rn(vv[0] - __bfloat162float(h0)),
                __float2bfloat16_rn(vv[1] - __bfloat162float(h1)));
            *(__nv_bfloat162*)&Bl[bk][bn + 2] = __nv_bfloat162(
                __float2bfloat16_rn(vv[2] - __bfloat162float(h2)),
                __float2bfloat16_rn(vv[3] - __bfloat162float(h3)));
        }
        __syncthreads();
#pragma unroll
        for (int ks = 0; ks < 2; ks++) {
            uint32_t ah[2][4], al[2][4];
#pragma unroll
            for (int i = 0; i < 2; i++) {
                uint32_t da = offA + (i * 16 * KP + ks * 16) * 2;
                ldsm4(ah[i][0], ah[i][1], ah[i][2], ah[i][3], baseAh + da);
                ldsm4(al[i][0], al[i][1], al[i][2], al[i][3], baseAl + da);
            }
#pragma unroll
            for (int jp = 0; jp < 4; jp++) {
                uint32_t db = offB + (ks * 16 * NP + jp * 16) * 2;
                uint32_t bh[4], bl[4];
                ldsm4t(bh[0], bh[1], bh[2], bh[3], baseBh + db);
                ldsm4t(bl[0], bl[1], bl[2], bl[3], baseBl + db);
#pragma unroll
                for (int jj = 0; jj < 2; jj++) {
                    int j = jp * 2 + jj;
#pragma unroll
                    for (int i = 0; i < 2; i++) {
                        asm volatile(
                            "mma.sync.aligned.m16n8k16.row.col.f32.bf16.bf16.f32 "
                            "{%0,%1,%2,%3},{%4,%5,%6,%7},{%8,%9},{%0,%1,%2,%3};"
                            : "+f"(acc[i][j][0]), "+f"(acc[i][j][1]),
                              "+f"(acc[i][j][2]), "+f"(acc[i][j][3])
                            : "r"(ah[i][0]), "r"(ah[i][1]), "r"(ah[i][2]), "r"(ah[i][3]),
                              "r"(bh[jj * 2]), "r"(bh[jj * 2 + 1]));
                        asm volatile(
                            "mma.sync.aligned.m16n8k16.row.col.f32.bf16.bf16.f32 "
                            "{%0,%1,%2,%3},{%4,%5,%6,%7},{%8,%9},{%0,%1,%2,%3};"
                            : "+f"(acc[i][j][0]), "+f"(acc[i][j][1]),
                              "+f"(acc[i][j][2]), "+f"(acc[i][j][3])
                            : "r"(ah[i][0]), "r"(ah[i][1]), "r"(ah[i][2]), "r"(ah[i][3]),
                              "r"(bl[jj * 2]), "r"(bl[jj * 2 + 1]));
                        asm volatile(
                            "mma.sync.aligned.m16n8k16.row.col.f32.bf16.bf16.f32 "
                            "{%0,%1,%2,%3},{%4,%5,%6,%7},{%8,%9},{%0,%1,%2,%3};"
                            : "+f"(acc[i][j][0]), "+f"(acc[i][j][1]),
                              "+f"(acc[i][j][2]), "+f"(acc[i][j][3])
                            : "r"(al[i][0]), "r"(al[i][1]), "r"(al[i][2]), "r"(al[i][3]),
                              "r"(bh[jj * 2]), "r"(bh[jj * 2 + 1]));
                    }
                }
            }
        }
        __syncthreads();
    }

    // epilogue: acc[i][j] = {(r,c),(r,c+1),(r+8,c),(r+8,c+1)}
    int rbase = row0 + wm * 32;
    int cbase = col0 + wn * 64;
#pragma unroll
    for (int j = 0; j < 8; j++) {
        int c0 = cbase + j * 8 + 2 * tig;
        float s0 = 1.f, s1 = 1.f, bb0 = 0.f, bb1 = 0.f;
        if (bptr) { bb0 = bptr[c0]; bb1 = bptr[c0 + 1]; }
        if (sptr) {
            s0 = sptr[c0]; s1 = sptr[c0 + 1];
            bb0 = bb0 * s0 + tptr[c0];
            bb1 = bb1 * s1 + tptr[c0 + 1];
        }
#pragma unroll
        for (int i = 0; i < 2; i++) {
            int r0 = rbase + i * 16 + gid;
#pragma unroll
            for (int h = 0; h < 2; h++) {
                int r = r0 + h * 8;
                if (r < nrows) {
                    float u0 = acc[i][j][h * 2 + 0] * s0 + bb0;
                    float u1 = acc[i][j][h * 2 + 1] * s1 + bb1;
                    if (act) { u0 = leaky(u0); u1 = leaky(u1); }
                    *(float2*)&C[(size_t)r * M + c0] = make_float2(u0, u1);
                }
            }
        }
    }
}

// ---------------- scatter: one warp per edge, red.v4.f32 ----------------
__global__ __launch_bounds__(256) void scatter0_kernel(const int* __restrict__ ei) {
    int e = blockIdx.x * 8 + (threadIdx.x >> 5);
    if (e >= N_EDGES) return;
    int lane = threadIdx.x & 31;
    int r = __ldg(&ei[e]);
    int c = __ldg(&ei[N_EDGES + e]);
    float coef = g_dis0[r] * g_dis0[c] * g_w0[e];
    float4 v = *(const float4*)&g_h0[(size_t)r * DIM + lane * 4];
    float4 o = make_float4(v.x * coef, v.y * coef, v.z * coef, v.w * coef);
    float* p = &g_a0[(size_t)c * DIM + lane * 4];
    asm volatile("red.global.add.v4.f32 [%0], {%1,%2,%3,%4};"
                 :: "l"(p), "f"(o.x), "f"(o.y), "f"(o.z), "f"(o.w) : "memory");
}

__global__ __launch_bounds__(256) void scatter1_kernel(const int* __restrict__ ei,
                                                       const int* __restrict__ cluster) {
    int e = blockIdx.x * 8 + (threadIdx.x >> 5);
    if (e >= N_EDGES) return;
    float w = g_w1[e];
    if (w == 0.f) return;          // masked (intra-cluster) or exactly-zero contribution
    int lane = threadIdx.x & 31;
    int r = __ldg(&ei[e]);
    int c = __ldg(&ei[N_EDGES + e]);
    int rp = __ldg(&cluster[r]);
    int cp = __ldg(&cluster[c]);
    float coef = g_dis1[rp] * g_dis1[cp] * w;
    float4 v = *(const float4*)&g_h1m[(size_t)rp * DIM + lane * 4];
    float4 o = make_float4(v.x * coef, v.y * coef, v.z * coef, v.w * coef);
    float* p = &g_a1[(size_t)cp * DIM + lane * 4];
    asm volatile("red.global.add.v4.f32 [%0], {%1,%2,%3,%4};"
                 :: "l"(p), "f"(o.x), "f"(o.y), "f"(o.z), "f"(o.w) : "memory");
}

// ---------------- fused post-layer0 + graclus pool ----------------
__global__ void post0_pool_kernel(const float* __restrict__ origin,
                                  const float* __restrict__ We, const float* __restrict__ be) {
    __shared__ float swself;
    if (threadIdx.x == 0) {
        float t = be[0];
        for (int k = 0; k < 12; k++) t += We[k];
        swself = t;
    }
    __syncthreads();
    int idx = blockIdx.x * blockDim.x + threadIdx.x;   // float4 index into xp
    if (idx >= NPOOL * (DIM / 4)) return;
    int j = idx >> 5;
    int d = idx & 31;
    float4 o;
    {
        int n = 2 * j;
        float ds = g_dis0[n];
        float sc = ds * ds * swself;
        float4 a  = ((const float4*)g_a0)[(size_t)n * 32 + d];
        float4 h  = ((const float4*)g_h0)[(size_t)n * 32 + d];
        float4 og = ((const float4*)origin)[(size_t)n * 32 + d];
        o.x = leaky(a.x + sc * h.x + og.x);
        o.y = leaky(a.y + sc * h.y + og.y);
        o.z = leaky(a.z + sc * h.z + og.z);
        o.w = leaky(a.w + sc * h.w + og.w);
    }
    {
        int n = 2 * j + 1;
        float ds = g_dis0[n];
        float sc = ds * ds * swself;
        float4 a  = ((const float4*)g_a0)[(size_t)n * 32 + d];
        float4 h  = ((const float4*)g_h0)[(size_t)n * 32 + d];
        float4 og = ((const float4*)origin)[(size_t)n * 32 + d];
        o.x = fmaxf(o.x, leaky(a.x + sc * h.x + og.x));
        o.y = fmaxf(o.y, leaky(a.y + sc * h.y + og.y));
        o.z = fmaxf(o.z, leaky(a.z + sc * h.z + og.z));
        o.w = fmaxf(o.w, leaky(a.w + sc * h.w + og.w));
    }
    ((float4*)g_xp)[idx] = o;
}

// ---------------- post layer1 + global max pool ----------------
// Warp handles 16 consecutive pooled nodes (batch_p sorted, runs ~390) and
// flushes block-local max with one atomic set per run segment.
__global__ __launch_bounds__(256) void post1_gmax_kernel(const int* __restrict__ batch_p,
                                                         const float* __restrict__ We,
                                                         const float* __restrict__ be) {
    __shared__ float swself;
    if (threadIdx.x == 0) {
        float t = be[0];
        for (int k = 0; k < 12; k++) t += We[k];
        swself = t;
    }
    __syncthreads();
    int warp_g = blockIdx.x * 8 + (threadIdx.x >> 5);
    int j0 = warp_g * 16;
    if (j0 >= NPOOL) return;
    int lane = threadIdx.x & 31;
    const float NEG = -3.0e38f;
    float m0 = NEG, m1 = NEG, m2 = NEG, m3 = NEG;
    int curb = __ldg(&batch_p[j0]);
#pragma unroll 4
    for (int t = 0; t < 16; t++) {
        int j = j0 + t;
        if (j >= NPOOL) break;
        int b = __ldg(&batch_p[j]);
        if (b != curb) {
            unsigned* gp = &g_gmax[curb * DIM + lane * 4];
            atomicMax(&gp[0], encf(m0)); atomicMax(&gp[1], encf(m1));
            atomicMax(&gp[2], encf(m2)); atomicMax(&gp[3], encf(m3));
            m0 = m1 = m2 = m3 = NEG;
            curb = b;
        }
        float ds = g_dis1[j];
        float sc = ds * ds * swself;
        float4 a  = ((const float4*)g_a1)[(size_t)j * 32 + lane];
        float4 hm = ((const float4*)g_h1m)[(size_t)j * 32 + lane];
        m0 = fmaxf(m0, leaky(a.x + sc * hm.x));
        m1 = fmaxf(m1, leaky(a.y + sc * hm.y));
        m2 = fmaxf(m2, leaky(a.z + sc * hm.z));
        m3 = fmaxf(m3, leaky(a.w + sc * hm.w));
    }
    unsigned* gp = &g_gmax[curb * DIM + lane * 4];
    atomicMax(&gp[0], encf(m0)); atomicMax(&gp[1], encf(m1));
    atomicMax(&gp[2], encf(m2)); atomicMax(&gp[3], encf(m3));
}

// ---------------- head MLP: [G,128] -> [G,64] -> [G,1] ----------------
__global__ void head_kernel(const float* __restrict__ W1, const float* __restrict__ b1,
                            const float* __restrict__ s, const float* __restrict__ t,
                            const float* __restrict__ W2, const float* __restrict__ b2,
                            float* __restrict__ out) {
    __shared__ float grow[128];
    __shared__ float red[64];
    int r = blockIdx.x;
    int h = threadIdx.x;  // 64 threads
    grow[h]      = decf(g_gmax[r * DIM + h]);
    grow[h + 64] = decf(g_gmax[r * DIM + h + 64]);
    __syncthreads();
    float acc = 0.f;
#pragma unroll 4
    for (int k = 0; k < 128; k++) acc += grow[k] * W1[k * 64 + h];
    float v = (acc + b1[h]) * s[h] + t[h];
    v = leaky(v);
    red[h] = v * W2[h];
    __syncthreads();
    if (h == 0) {
        float total = b2[0];
        for (int k = 0; k < 64; k++) total += red[k];
        out[r] = total;
    }
}

// ---------------- launch ----------------
extern "C" void kernel_launch(void* const* d_in, const int* in_sizes, int n_in,
                              void* d_out, int out_size) {
    const float* x = (const float*)d_in[0];
    const float* origin;
    const float* ea;
    const int* ei;
    if (in_sizes[1] == N_NODES * DIM) {        // dict order: x, origin, edge_attr, edge_index
        origin = (const float*)d_in[1];
        ea     = (const float*)d_in[2];
        ei     = (const int*)d_in[3];
    } else {                                    // signature order: x, edge_index, edge_attr, origin
        ei     = (const int*)d_in[1];
        ea     = (const float*)d_in[2];
        origin = (const float*)d_in[3];
    }
    const int* cluster = (const int*)d_in[4];
    const int* batch_p = (const int*)d_in[5];
    const float* l0_W1 = (const float*)d_in[6];
    const float* l0_b1 = (const float*)d_in[7];
    const float* l0_s  = (const float*)d_in[8];
    const float* l0_t  = (const float*)d_in[9];
    const float* l0_W2 = (const float*)d_in[10];
    const float* l0_b2 = (const float*)d_in[11];
    const float* l0_We = (const float*)d_in[12];
    const float* l0_be = (const float*)d_in[13];
    const float* l1_W1 = (const float*)d_in[14];
    const float* l1_b1 = (const float*)d_in[15];
    const float* l1_s  = (const float*)d_in[16];
    const float* l1_t  = (const float*)d_in[17];
    const float* l1_W2 = (const float*)d_in[18];
    const float* l1_b2 = (const float*)d_in[19];
    const float* l1_We = (const float*)d_in[20];
    const float* l1_be = (const float*)d_in[21];
    const float* hd_W1 = (const float*)d_in[22];
    const float* hd_b1 = (const float*)d_in[23];
    const float* hd_s  = (const float*)d_in[24];
    const float* hd_t  = (const float*)d_in[25];
    const float* hd_W2 = (const float*)d_in[26];
    const float* hd_b2 = (const float*)d_in[27];
    float* out = (float*)d_out;

    float *p_h0, *p_t1, *p_xp, *p_h1m;
    cudaGetSymbolAddress((void**)&p_h0,  g_h0);
    cudaGetSymbolAddress((void**)&p_t1,  g_t1);
    cudaGetSymbolAddress((void**)&p_xp,  g_xp);
    cudaGetSymbolAddress((void**)&p_h1m, g_h1m);

    zero_kernel<<<2048, 256>>>();
    edge_kernel<<<(N_EDGES + 255) / 256, 256>>>(ei, ea, cluster, l0_We, l0_be, l1_We, l1_be);
    dis_kernel<<<(N_NODES + 255) / 256, 256>>>();

    // MLP0: t1 = leaky((x@W1)*s + b1*s + t);  h0 = t1@W2 + b2
    bf16x3_gemm_kernel<<<dim3((N_NODES + 127) / 128, 1), 256>>>(
        x, l0_W1, l0_b1, l0_s, l0_t, p_t1, N_NODES, 128, 128, 1);
    bf16x3_gemm_kernel<<<dim3((N_NODES + 127) / 128, 1), 256>>>(
        p_t1, l0_W2, l0_b2, nullptr, nullptr, p_h0, N_NODES, 128, 128, 0);

    scatter0_kernel<<<(N_EDGES + 7) / 8, 256>>>(ei);
    post0_pool_kernel<<<(NPOOL * 32 + 255) / 256, 256>>>(origin, l0_We, l0_be);

    // MLP1: t1 = leaky((xp@W1)*s + b1*s + t) [NPOOL,256];  h1m = t1@W2 + b2
    bf16x3_gemm_kernel<<<dim3((NPOOL + 127) / 128, 2), 256>>>(
        p_xp, l1_W1, l1_b1, l1_s, l1_t, p_t1, NPOOL, 128, 256, 1);
    bf16x3_gemm_kernel<<<dim3((NPOOL + 127) / 128, 1), 256>>>(
        p_t1, l1_W2, l1_b2, nullptr, nullptr, p_h1m, NPOOL, 256, 128, 0);

    scatter1_kernel<<<(N_EDGES + 7) / 8, 256>>>(ei, cluster);
    post1_gmax_kernel<<<(NPOOL + 127) / 128, 256>>>(batch_p, l1_We, l1_be);
    head_kernel<<<NGRAPH, 64>>>(hd_W1, hd_b1, hd_s, hd_t, hd_W2, hd_b2, out);
}

// round 5
// speedup vs baseline: 1.7195x; 1.2684x over previous
#include <cuda_runtime.h>
#include <cuda_bf16.h>
#include <cstdint>

#define N_NODES 50000
#define N_EDGES 800000
#define NPOOL   25000
#define DIM     128
#define HID     256
#define NGRAPH  64
#define NTOT    75000          // cnt/off space: [0,50000) layer0 by col, [50000,75000) layer1 by colp
#define NBLK    293            // ceil(75000/256)

// ---------------- scratch (static __device__, no allocation) ----------------
__device__ float g_h0 [N_NODES * DIM];   // MLP0 output
__device__ float g_t1 [N_NODES * DIM];   // GEMM intermediate (also NPOOL*HID view)
__device__ float g_xp [NPOOL * DIM];     // pooled features
__device__ float g_h1m[NPOOL * DIM];     // MLP1 output
__device__ int   g_cnt[NTOT];            // in-degree buckets
__device__ int   g_off[NTOT];            // exclusive offsets
__device__ int   g_cur[NTOT];            // fill cursors
__device__ int   g_part[512];            // scan partials
__device__ int   g_srcA[2 * N_EDGES];    // CSR payload: source node
__device__ float g_cfA [2 * N_EDGES];    // CSR payload: coefficient
__device__ int   g_deg0[N_NODES];        // out-degree by row (normalization)
__device__ int   g_deg1[NPOOL];
__device__ float g_dis0[N_NODES];
__device__ float g_dis1[NPOOL];
__device__ unsigned g_gmax[NGRAPH * DIM];

// ---------------- helpers ----------------
__device__ __forceinline__ unsigned encf(float f) {
    unsigned u = __float_as_uint(f);
    return (u & 0x80000000u) ? ~u : (u | 0x80000000u);
}
__device__ __forceinline__ float decf(unsigned k) {
    return (k & 0x80000000u) ? __uint_as_float(k & 0x7FFFFFFFu) : __uint_as_float(~k);
}
__device__ __forceinline__ float leaky(float v) { return v > 0.f ? v : 0.01f * v; }

__device__ __forceinline__ void ldsm4(uint32_t& r0, uint32_t& r1, uint32_t& r2, uint32_t& r3,
                                      uint32_t addr) {
    asm volatile("ldmatrix.sync.aligned.m8n8.x4.shared.b16 {%0,%1,%2,%3}, [%4];"
                 : "=r"(r0), "=r"(r1), "=r"(r2), "=r"(r3) : "r"(addr));
}
__device__ __forceinline__ void ldsm4t(uint32_t& r0, uint32_t& r1, uint32_t& r2, uint32_t& r3,
                                       uint32_t addr) {
    asm volatile("ldmatrix.sync.aligned.m8n8.x4.trans.shared.b16 {%0,%1,%2,%3}, [%4];"
                 : "=r"(r0), "=r"(r1), "=r"(r2), "=r"(r3) : "r"(addr));
}

// ---------------- zero counters ----------------
__global__ void zero_kernel() {
    int i = blockIdx.x * blockDim.x + threadIdx.x;
    int stride = gridDim.x * blockDim.x;
    for (int k = i; k < NTOT; k += stride) g_cnt[k] = 0;
    for (int k = i; k < N_NODES; k += stride) g_deg0[k] = 0;
    for (int k = i; k < NPOOL; k += stride) g_deg1[k] = 0;
    for (int k = i; k < NGRAPH * DIM; k += stride) g_gmax[k] = 0u;
}

// ---------------- count: out-degrees (norm) + in-degree buckets (CSR) ----------------
__global__ void count_kernel(const int* __restrict__ ei, const int* __restrict__ cluster) {
    int e = blockIdx.x * blockDim.x + threadIdx.x;
    if (e >= N_EDGES) return;
    int r = __ldg(&ei[e]);
    int c = __ldg(&ei[N_EDGES + e]);
    atomicAdd(&g_deg0[r], 1);
    atomicAdd(&g_cnt[c], 1);
    int rp = __ldg(&cluster[r]), cp = __ldg(&cluster[c]);
    if (rp != cp) {
        atomicAdd(&g_deg1[rp], 1);
        atomicAdd(&g_cnt[N_NODES + cp], 1);
    }
}

__global__ void dis_kernel() {
    int i = blockIdx.x * blockDim.x + threadIdx.x;
    if (i < N_NODES) g_dis0[i] = rsqrtf((float)g_deg0[i] + 1.0f);
    if (i < NPOOL)   g_dis1[i] = rsqrtf((float)g_deg1[i] + 1.0f);
}

// ---------------- exclusive scan over g_cnt (3 kernels) ----------------
__global__ void scan_part_kernel() {
    __shared__ int sh[256];
    int i = blockIdx.x * 256 + threadIdx.x;
    int v = (i < NTOT) ? g_cnt[i] : 0;
    sh[threadIdx.x] = v;
    __syncthreads();
#pragma unroll
    for (int d = 1; d < 256; d <<= 1) {
        int t = (threadIdx.x >= d) ? sh[threadIdx.x - d] : 0;
        __syncthreads();
        sh[threadIdx.x] += t;
        __syncthreads();
    }
    if (i < NTOT) g_off[i] = sh[threadIdx.x];   // inclusive within block
    if (threadIdx.x == 255) g_part[blockIdx.x] = sh[255];
}

__global__ void scan_part2_kernel() {
    __shared__ int sh[512];
    int v = (threadIdx.x < NBLK) ? g_part[threadIdx.x] : 0;
    sh[threadIdx.x] = v;
    __syncthreads();
#pragma unroll
    for (int d = 1; d < 512; d <<= 1) {
        int t = (threadIdx.x >= d) ? sh[threadIdx.x - d] : 0;
        __syncthreads();
        sh[threadIdx.x] += t;
        __syncthreads();
    }
    if (threadIdx.x < NBLK) g_part[threadIdx.x] = sh[threadIdx.x] - v;  // exclusive
}

__global__ void scan_final_kernel() {
    int i = blockIdx.x * 256 + threadIdx.x;
    if (i >= NTOT) return;
    int excl = g_off[i] - g_cnt[i] + g_part[blockIdx.x];
    g_off[i] = excl;
    g_cur[i] = excl;
}

// ---------------- fill: edge weights + coefficients into CSR buckets ----------------
__global__ void fill_kernel(const int* __restrict__ ei, const float* __restrict__ ea,
                            const int* __restrict__ cluster,
                            const float* __restrict__ We0, const float* __restrict__ be0,
                            const float* __restrict__ We1, const float* __restrict__ be1) {
    __shared__ float sW0[12], sW1[12], sb0, sb1;
    int t = threadIdx.x;
    if (t < 12) sW0[t] = We0[t];
    else if (t < 24) sW1[t - 12] = We1[t - 12];
    if (t == 24) sb0 = be0[0];
    if (t == 25) sb1 = be1[0];
    __syncthreads();

    int e = blockIdx.x * blockDim.x + t;
    if (e >= N_EDGES) return;
    const float* a = ea + (size_t)e * 12;
    float w0 = sb0, w1 = sb1;
#pragma unroll
    for (int k = 0; k < 12; k++) { float av = a[k]; w0 += av * sW0[k]; w1 += av * sW1[k]; }
    int r = __ldg(&ei[e]);
    int c = __ldg(&ei[N_EDGES + e]);
    float cf0 = g_dis0[r] * g_dis0[c] * w0;
    int p = atomicAdd(&g_cur[c], 1);
    g_srcA[p] = r;
    g_cfA[p]  = cf0;
    int rp = __ldg(&cluster[r]), cp = __ldg(&cluster[c]);
    if (rp != cp) {
        float cf1 = g_dis1[rp] * g_dis1[cp] * w1;
        int q = atomicAdd(&g_cur[N_NODES + cp], 1);
        g_srcA[q] = rp;
        g_cfA[q]  = cf1;
    }
}

// ---------------- bf16 3-term split-precision tensor-core GEMM (ldmatrix) ----------------
#define KP 40
#define NP 136
__global__ __launch_bounds__(256, 2) void bf16x3_gemm_kernel(
    const float* __restrict__ A, const float* __restrict__ W,
    const float* __restrict__ bptr, const float* __restrict__ sptr, const float* __restrict__ tptr,
    float* __restrict__ C, int nrows, int K, int M, int act) {
    __shared__ __nv_bfloat16 Ah[128][KP];
    __shared__ __nv_bfloat16 Al[128][KP];
    __shared__ __nv_bfloat16 Bh[32][NP];
    __shared__ __nv_bfloat16 Bl[32][NP];
    int row0 = blockIdx.x * 128;
    int col0 = blockIdx.y * 128;
    int tid = threadIdx.x;
    int wid = tid >> 5, lane = tid & 31;
    int wm = wid & 3;
    int wn = wid >> 2;
    int gid = lane >> 2, tig = lane & 3;
    int sub = lane >> 3, lr = lane & 7;

    uint32_t baseAh = (uint32_t)__cvta_generic_to_shared(&Ah[0][0]);
    uint32_t baseAl = (uint32_t)__cvta_generic_to_shared(&Al[0][0]);
    uint32_t baseBh = (uint32_t)__cvta_generic_to_shared(&Bh[0][0]);
    uint32_t baseBl = (uint32_t)__cvta_generic_to_shared(&Bl[0][0]);
    uint32_t offA = ((wm * 32 + (sub & 1) * 8 + lr) * KP + (sub >> 1) * 8) * 2;
    uint32_t offB = (((sub & 1) * 8 + lr) * NP + wn * 64 + (sub >> 1) * 8) * 2;

    float acc[2][8][4];
#pragma unroll
    for (int i = 0; i < 2; i++)
#pragma unroll
        for (int j = 0; j < 8; j++)
#pragma unroll
            for (int q = 0; q < 4; q++) acc[i][j][q] = 0.f;

    for (int kk = 0; kk < K; kk += 32) {
#pragma unroll
        for (int l = 0; l < 4; l++) {
            int f = tid + l * 256;
            int ar = f >> 3;
            int ak = (f & 7) * 4;
            int grow = row0 + ar;
            float4 v = make_float4(0.f, 0.f, 0.f, 0.f);
            if (grow < nrows) v = *(const float4*)&A[(size_t)grow * K + kk + ak];
            float vv[4] = {v.x, v.y, v.z, v.w};
            __nv_bfloat16 h0 = __float2bfloat16_rn(vv[0]);
            __nv_bfloat16 h1 = __float2bfloat16_rn(vv[1]);
            __nv_bfloat16 h2 = __float2bfloat16_rn(vv[2]);
            __nv_bfloat16 h3 = __float2bfloat16_rn(vv[3]);
            *(__nv_bfloat162*)&Ah[ar][ak]     = __nv_bfloat162(h0, h1);
            *(__nv_bfloat162*)&Ah[ar][ak + 2] = __nv_bfloat162(h2, h3);
            *(__nv_bfloat162*)&Al[ar][ak] = __nv_bfloat162(
                __float2bfloat16_rn(vv[0] - __bfloat162float(h0)),
                __float2bfloat16_rn(vv[1] - __bfloat162float(h1)));
            *(__nv_bfloat162*)&Al[ar][ak + 2] = __nv_bfloat162(
                __float2bfloat16_rn(vv[2] - __bfloat162float(h2)),
                __float2bfloat16_rn(vv[3] - __bfloat162float(h3)));
        }
#pragma unroll
        for (int l = 0; l < 4; l++) {
            int f = tid + l * 256;
            int bk = f >> 5;
            int bn = (f & 31) * 4;
            float4 v = *(const float4*)&W[(size_t)(kk + bk) * M + col0 + bn];
            float vv[4] = {v.x, v.y, v.z, v.w};
            __nv_bfloat16 h0 = __float2bfloat16_rn(vv[0]);
            __nv_bfloat16 h1 = __float2bfloat16_rn(vv[1]);
            __nv_bfloat16 h2 = __float2bfloat16_rn(vv[2]);
            __nv_bfloat16 h3 = __float2bfloat16_rn(vv[3]);
            *(__nv_bfloat162*)&Bh[bk][bn]     = __nv_bfloat162(h0, h1);
            *(__nv_bfloat162*)&Bh[bk][bn + 2] = __nv_bfloat162(h2, h3);
            *(__nv_bfloat162*)&Bl[bk][bn] = __nv_bfloat162(
                __float2bfloat16_rn(vv[0] - __bfloat162float(h0)),
                __float2bfloat16_rn(vv[1] - __bfloat162float(h1)));
            *(__nv_bfloat162*)&Bl[bk][bn + 2] = __nv_bfloat162(
                __float2bfloat16_rn(vv[2] - __bfloat162float(h2)),
                __float2bfloat16_rn(vv[3] - __bfloat162float(h3)));
        }
        __syncthreads();
#pragma unroll
        for (int ks = 0; ks < 2; ks++) {
            uint32_t ah[2][4], al[2][4];
#pragma unroll
            for (int i = 0; i < 2; i++) {
                uint32_t da = offA + (i * 16 * KP + ks * 16) * 2;
                ldsm4(ah[i][0], ah[i][1], ah[i][2], ah[i][3], baseAh + da);
                ldsm4(al[i][0], al[i][1], al[i][2], al[i][3], baseAl + da);
            }
#pragma unroll
            for (int jp = 0; jp < 4; jp++) {
                uint32_t db = offB + (ks * 16 * NP + jp * 16) * 2;
                uint32_t bh[4], bl[4];
                ldsm4t(bh[0], bh[1], bh[2], bh[3], baseBh + db);
                ldsm4t(bl[0], bl[1], bl[2], bl[3], baseBl + db);
#pragma unroll
                for (int jj = 0; jj < 2; jj++) {
                    int j = jp * 2 + jj;
#pragma unroll
                    for (int i = 0; i < 2; i++) {
                        asm volatile(
                            "mma.sync.aligned.m16n8k16.row.col.f32.bf16.bf16.f32 "
                            "{%0,%1,%2,%3},{%4,%5,%6,%7},{%8,%9},{%0,%1,%2,%3};"
                            : "+f"(acc[i][j][0]), "+f"(acc[i][j][1]),
                              "+f"(acc[i][j][2]), "+f"(acc[i][j][3])
                            : "r"(ah[i][0]), "r"(ah[i][1]), "r"(ah[i][2]), "r"(ah[i][3]),
                              "r"(bh[jj * 2]), "r"(bh[jj * 2 + 1]));
                        asm volatile(
                            "mma.sync.aligned.m16n8k16.row.col.f32.bf16.bf16.f32 "
                            "{%0,%1,%2,%3},{%4,%5,%6,%7},{%8,%9},{%0,%1,%2,%3};"
                            : "+f"(acc[i][j][0]), "+f"(acc[i][j][1]),
                              "+f"(acc[i][j][2]), "+f"(acc[i][j][3])
                            : "r"(ah[i][0]), "r"(ah[i][1]), "r"(ah[i][2]), "r"(ah[i][3]),
                              "r"(bl[jj * 2]), "r"(bl[jj * 2 + 1]));
                        asm volatile(
                            "mma.sync.aligned.m16n8k16.row.col.f32.bf16.bf16.f32 "
                            "{%0,%1,%2,%3},{%4,%5,%6,%7},{%8,%9},{%0,%1,%2,%3};"
                            : "+f"(acc[i][j][0]), "+f"(acc[i][j][1]),
                              "+f"(acc[i][j][2]), "+f"(acc[i][j][3])
                            : "r"(al[i][0]), "r"(al[i][1]), "r"(al[i][2]), "r"(al[i][3]),
                              "r"(bh[jj * 2]), "r"(bh[jj * 2 + 1]));
                    }
                }
            }
        }
        __syncthreads();
    }

    int rbase = row0 + wm * 32;
    int cbase = col0 + wn * 64;
#pragma unroll
    for (int j = 0; j < 8; j++) {
        int c0 = cbase + j * 8 + 2 * tig;
        float s0 = 1.f, s1 = 1.f, bb0 = 0.f, bb1 = 0.f;
        if (bptr) { bb0 = bptr[c0]; bb1 = bptr[c0 + 1]; }
        if (sptr) {
            s0 = sptr[c0]; s1 = sptr[c0 + 1];
            bb0 = bb0 * s0 + tptr[c0];
            bb1 = bb1 * s1 + tptr[c0 + 1];
        }
#pragma unroll
        for (int i = 0; i < 2; i++) {
            int r0 = rbase + i * 16 + gid;
#pragma unroll
            for (int h = 0; h < 2; h++) {
                int r = r0 + h * 8;
                if (r < nrows) {
                    float u0 = acc[i][j][h * 2 + 0] * s0 + bb0;
                    float u1 = acc[i][j][h * 2 + 1] * s1 + bb1;
                    if (act) { u0 = leaky(u0); u1 = leaky(u1); }
                    *(float2*)&C[(size_t)r * M + c0] = make_float2(u0, u1);
                }
            }
        }
    }
}

// ---------------- gather layer0 + post + graclus pool (warp per pooled node) ----------------
__global__ __launch_bounds__(256) void gather0_pool_kernel(const float* __restrict__ origin,
                                                           const float* __restrict__ We,
                                                           const float* __restrict__ be) {
    __shared__ float swself;
    if (threadIdx.x == 0) {
        float t = be[0];
        for (int k = 0; k < 12; k++) t += We[k];
        swself = t;
    }
    __syncthreads();
    int j = blockIdx.x * 8 + (threadIdx.x >> 5);
    if (j >= NPOOL) return;
    int lane = threadIdx.x & 31;
    float4 vmax;
#pragma unroll
    for (int t = 0; t < 2; t++) {
        int n = 2 * j + t;
        int base = g_off[n];
        int cnt = g_cnt[n];
        float4 a0 = make_float4(0.f, 0.f, 0.f, 0.f);
        float4 a1 = make_float4(0.f, 0.f, 0.f, 0.f);
        int k = 0;
        for (; k + 2 <= cnt; k += 2) {
            int s0 = __ldg(&g_srcA[base + k]);
            int s1 = __ldg(&g_srcA[base + k + 1]);
            float c0 = __ldg(&g_cfA[base + k]);
            float c1 = __ldg(&g_cfA[base + k + 1]);
            float4 v0 = *(const float4*)&g_h0[(size_t)s0 * DIM + lane * 4];
            float4 v1 = *(const float4*)&g_h0[(size_t)s1 * DIM + lane * 4];
            a0.x += c0 * v0.x; a0.y += c0 * v0.y; a0.z += c0 * v0.z; a0.w += c0 * v0.w;
            a1.x += c1 * v1.x; a1.y += c1 * v1.y; a1.z += c1 * v1.z; a1.w += c1 * v1.w;
        }
        if (k < cnt) {
            int s0 = __ldg(&g_srcA[base + k]);
            float c0 = __ldg(&g_cfA[base + k]);
            float4 v0 = *(const float4*)&g_h0[(size_t)s0 * DIM + lane * 4];
            a0.x += c0 * v0.x; a0.y += c0 * v0.y; a0.z += c0 * v0.z; a0.w += c0 * v0.w;
        }
        float ds = g_dis0[n];
        float sc = ds * ds * swself;
        float4 h  = *(const float4*)&g_h0[(size_t)n * DIM + lane * 4];
        float4 og = *(const float4*)&origin[(size_t)n * DIM + lane * 4];
        float4 v;
        v.x = leaky(a0.x + a1.x + sc * h.x + og.x);
        v.y = leaky(a0.y + a1.y + sc * h.y + og.y);
        v.z = leaky(a0.z + a1.z + sc * h.z + og.z);
        v.w = leaky(a0.w + a1.w + sc * h.w + og.w);
        if (t == 0) vmax = v;
        else {
            vmax.x = fmaxf(vmax.x, v.x); vmax.y = fmaxf(vmax.y, v.y);
            vmax.z = fmaxf(vmax.z, v.z); vmax.w = fmaxf(vmax.w, v.w);
        }
    }
    *(float4*)&g_xp[(size_t)j * DIM + lane * 4] = vmax;
}

// ---------------- gather layer1 + post + global max pool (warp per pooled node) ----------------
__global__ __launch_bounds__(256) void gather1_gmax_kernel(const int* __restrict__ batch_p,
                                                           const float* __restrict__ We,
                                                           const float* __restrict__ be) {
    __shared__ float swself;
    if (threadIdx.x == 0) {
        float t = be[0];
        for (int k = 0; k < 12; k++) t += We[k];
        swself = t;
    }
    __syncthreads();
    int j = blockIdx.x * 8 + (threadIdx.x >> 5);
    if (j >= NPOOL) return;
    int lane = threadIdx.x & 31;
    int base = g_off[N_NODES + j];
    int cnt = g_cnt[N_NODES + j];
    float4 a0 = make_float4(0.f, 0.f, 0.f, 0.f);
    float4 a1 = make_float4(0.f, 0.f, 0.f, 0.f);
    int k = 0;
    for (; k + 2 <= cnt; k += 2) {
        int s0 = __ldg(&g_srcA[base + k]);
        int s1 = __ldg(&g_srcA[base + k + 1]);
        float c0 = __ldg(&g_cfA[base + k]);
        float c1 = __ldg(&g_cfA[base + k + 1]);
        float4 v0 = *(const float4*)&g_h1m[(size_t)s0 * DIM + lane * 4];
        float4 v1 = *(const float4*)&g_h1m[(size_t)s1 * DIM + lane * 4];
        a0.x += c0 * v0.x; a0.y += c0 * v0.y; a0.z += c0 * v0.z; a0.w += c0 * v0.w;
        a1.x += c1 * v1.x; a1.y += c1 * v1.y; a1.z += c1 * v1.z; a1.w += c1 * v1.w;
    }
    if (k < cnt) {
        int s0 = __ldg(&g_srcA[base + k]);
        float c0 = __ldg(&g_cfA[base + k]);
        float4 v0 = *(const float4*)&g_h1m[(size_t)s0 * DIM + lane * 4];
        a0.x += c0 * v0.x; a0.y += c0 * v0.y; a0.z += c0 * v0.z; a0.w += c0 * v0.w;
    }
    float ds = g_dis1[j];
    float sc = ds * ds * swself;
    float4 hm = *(const float4*)&g_h1m[(size_t)j * DIM + lane * 4];
    float v0 = leaky(a0.x + a1.x + sc * hm.x);
    float v1 = leaky(a0.y + a1.y + sc * hm.y);
    float v2 = leaky(a0.z + a1.z + sc * hm.z);
    float v3 = leaky(a0.w + a1.w + sc * hm.w);
    int b = __ldg(&batch_p[j]);
    unsigned* gp = &g_gmax[b * DIM + lane * 4];
    atomicMax(&gp[0], encf(v0)); atomicMax(&gp[1], encf(v1));
    atomicMax(&gp[2], encf(v2)); atomicMax(&gp[3], encf(v3));
}

// ---------------- head MLP: [G,128] -> [G,64] -> [G,1] ----------------
__global__ void head_kernel(const float* __restrict__ W1, const float* __restrict__ b1,
                            const float* __restrict__ s, const float* __restrict__ t,
                            const float* __restrict__ W2, const float* __restrict__ b2,
                            float* __restrict__ out) {
    __shared__ float grow[128];
    __shared__ float red[64];
    int r = blockIdx.x;
    int h = threadIdx.x;
    grow[h]      = decf(g_gmax[r * DIM + h]);
    grow[h + 64] = decf(g_gmax[r * DIM + h + 64]);
    __syncthreads();
    float acc = 0.f;
#pragma unroll 4
    for (int k = 0; k < 128; k++) acc += grow[k] * W1[k * 64 + h];
    float v = (acc + b1[h]) * s[h] + t[h];
    v = leaky(v);
    red[h] = v * W2[h];
    __syncthreads();
    if (h == 0) {
        float total = b2[0];
        for (int k = 0; k < 64; k++) total += red[k];
        out[r] = total;
    }
}

// ---------------- launch ----------------
extern "C" void kernel_launch(void* const* d_in, const int* in_sizes, int n_in,
                              void* d_out, int out_size) {
    const float* x = (const float*)d_in[0];
    const float* origin;
    const float* ea;
    const int* ei;
    if (in_sizes[1] == N_NODES * DIM) {
        origin = (const float*)d_in[1];
        ea     = (const float*)d_in[2];
        ei     = (const int*)d_in[3];
    } else {
        ei     = (const int*)d_in[1];
        ea     = (const float*)d_in[2];
        origin = (const float*)d_in[3];
    }
    const int* cluster = (const int*)d_in[4];
    const int* batch_p = (const int*)d_in[5];
    const float* l0_W1 = (const float*)d_in[6];
    const float* l0_b1 = (const float*)d_in[7];
    const float* l0_s  = (const float*)d_in[8];
    const float* l0_t  = (const float*)d_in[9];
    const float* l0_W2 = (const float*)d_in[10];
    const float* l0_b2 = (const float*)d_in[11];
    const float* l0_We = (const float*)d_in[12];
    const float* l0_be = (const float*)d_in[13];
    const float* l1_W1 = (const float*)d_in[14];
    const float* l1_b1 = (const float*)d_in[15];
    const float* l1_s  = (const float*)d_in[16];
    const float* l1_t  = (const float*)d_in[17];
    const float* l1_W2 = (const float*)d_in[18];
    const float* l1_b2 = (const float*)d_in[19];
    const float* l1_We = (const float*)d_in[20];
    const float* l1_be = (const float*)d_in[21];
    const float* hd_W1 = (const float*)d_in[22];
    const float* hd_b1 = (const float*)d_in[23];
    const float* hd_s  = (const float*)d_in[24];
    const float* hd_t  = (const float*)d_in[25];
    const float* hd_W2 = (const float*)d_in[26];
    const float* hd_b2 = (const float*)d_in[27];
    float* out = (float*)d_out;

    float *p_h0, *p_t1, *p_xp, *p_h1m;
    cudaGetSymbolAddress((void**)&p_h0,  g_h0);
    cudaGetSymbolAddress((void**)&p_t1,  g_t1);
    cudaGetSymbolAddress((void**)&p_xp,  g_xp);
    cudaGetSymbolAddress((void**)&p_h1m, g_h1m);

    zero_kernel<<<256, 256>>>();
    count_kernel<<<(N_EDGES + 255) / 256, 256>>>(ei, cluster);
    dis_kernel<<<(N_NODES + 255) / 256, 256>>>();
    scan_part_kernel<<<NBLK, 256>>>();
    scan_part2_kernel<<<1, 512>>>();
    scan_final_kernel<<<NBLK, 256>>>();
    fill_kernel<<<(N_EDGES + 255) / 256, 256>>>(ei, ea, cluster, l0_We, l0_be, l1_We, l1_be);

    // MLP0: t1 = leaky((x@W1)*s + b1*s + t);  h0 = t1@W2 + b2
    bf16x3_gemm_kernel<<<dim3((N_NODES + 127) / 128, 1), 256>>>(
        x, l0_W1, l0_b1, l0_s, l0_t, p_t1, N_NODES, 128, 128, 1);
    bf16x3_gemm_kernel<<<dim3((N_NODES + 127) / 128, 1), 256>>>(
        p_t1, l0_W2, l0_b2, nullptr, nullptr, p_h0, N_NODES, 128, 128, 0);

    gather0_pool_kernel<<<(NPOOL + 7) / 8, 256>>>(origin, l0_We, l0_be);

    // MLP1: t1 = leaky((xp@W1)*s + b1*s + t) [NPOOL,256];  h1m = t1@W2 + b2
    bf16x3_gemm_kernel<<<dim3((NPOOL + 127) / 128, 2), 256>>>(
        p_xp, l1_W1, l1_b1, l1_s, l1_t, p_t1, NPOOL, 128, 256, 1);
    bf16x3_gemm_kernel<<<dim3((NPOOL + 127) / 128, 1), 256>>>(
        p_t1, l1_W2, l1_b2, nullptr, nullptr, p_h1m, NPOOL, 256, 128, 0);

    gather1_gmax_kernel<<<(NPOOL + 7) / 8, 256>>>(batch_p, l1_We, l1_be);
    head_kernel<<<NGRAPH, 64>>>(hd_W1, hd_b1, hd_s, hd_t, hd_W2, hd_b2, out);
}

// round 6
// speedup vs baseline: 1.7627x; 1.0251x over previous
#include <cuda_runtime.h>
#include <cuda_bf16.h>
#include <cstdint>

#define N_NODES 50000
#define N_EDGES 800000
#define NPOOL   25000
#define DIM     128
#define HID     256
#define NGRAPH  64
#define NTOT    75000          // cnt/off space: [0,50000) layer0 by col, [50000,75000) layer1 by colp
#define NBLK    293            // ceil(75000/256)
#define AUXBLK  625            // aux blocks appended to hybrid GEMM launches

// ---------------- scratch (static __device__, no allocation) ----------------
__device__ float g_h0 [N_NODES * DIM];   // MLP0 output
__device__ float g_t1 [N_NODES * DIM];   // GEMM intermediate (also NPOOL*HID view)
__device__ float g_xp [NPOOL * DIM];     // pooled features
__device__ float g_h1m[NPOOL * DIM];     // MLP1 output
__device__ int   g_cnt[NTOT];            // in-degree buckets
__device__ int   g_off[NTOT];            // exclusive offsets
__device__ int   g_cur[NTOT];            // fill cursors
__device__ int   g_part[512];            // scan partials
__device__ int   g_srcA[2 * N_EDGES];    // CSR payload: source node
__device__ float g_cfA [2 * N_EDGES];    // CSR payload: coefficient
__device__ int   g_deg0[N_NODES];        // out-degree by row (normalization)
__device__ int   g_deg1[NPOOL];
__device__ float g_dis0[N_NODES];
__device__ float g_dis1[NPOOL];
__device__ unsigned g_gmax[NGRAPH * DIM];

// ---------------- helpers ----------------
__device__ __forceinline__ unsigned encf(float f) {
    unsigned u = __float_as_uint(f);
    return (u & 0x80000000u) ? ~u : (u | 0x80000000u);
}
__device__ __forceinline__ float decf(unsigned k) {
    return (k & 0x80000000u) ? __uint_as_float(k & 0x7FFFFFFFu) : __uint_as_float(~k);
}
__device__ __forceinline__ float leaky(float v) { return v > 0.f ? v : 0.01f * v; }

__device__ __forceinline__ void ldsm4(uint32_t& r0, uint32_t& r1, uint32_t& r2, uint32_t& r3,
                                      uint32_t addr) {
    asm volatile("ldmatrix.sync.aligned.m8n8.x4.shared.b16 {%0,%1,%2,%3}, [%4];"
                 : "=r"(r0), "=r"(r1), "=r"(r2), "=r"(r3) : "r"(addr));
}
__device__ __forceinline__ void ldsm4t(uint32_t& r0, uint32_t& r1, uint32_t& r2, uint32_t& r3,
                                       uint32_t addr) {
    asm volatile("ldmatrix.sync.aligned.m8n8.x4.trans.shared.b16 {%0,%1,%2,%3}, [%4];"
                 : "=r"(r0), "=r"(r1), "=r"(r2), "=r"(r3) : "r"(addr));
}

// ---------------- zero counters ----------------
__global__ void zero_kernel() {
    int i = blockIdx.x * blockDim.x + threadIdx.x;
    int stride = gridDim.x * blockDim.x;
    for (int k = i; k < NTOT; k += stride) g_cnt[k] = 0;
    for (int k = i; k < N_NODES; k += stride) g_deg0[k] = 0;
    for (int k = i; k < NPOOL; k += stride) g_deg1[k] = 0;
    for (int k = i; k < NGRAPH * DIM; k += stride) g_gmax[k] = 0u;
}

// ---------------- exclusive scan over g_cnt (3 kernels) ----------------
__global__ void scan_part_kernel() {
    __shared__ int sh[256];
    int i = blockIdx.x * 256 + threadIdx.x;
    int v = (i < NTOT) ? g_cnt[i] : 0;
    sh[threadIdx.x] = v;
    __syncthreads();
#pragma unroll
    for (int d = 1; d < 256; d <<= 1) {
        int t = (threadIdx.x >= d) ? sh[threadIdx.x - d] : 0;
        __syncthreads();
        sh[threadIdx.x] += t;
        __syncthreads();
    }
    if (i < NTOT) g_off[i] = sh[threadIdx.x];   // inclusive within block
    if (threadIdx.x == 255) g_part[blockIdx.x] = sh[255];
}

__global__ void scan_part2_kernel() {
    __shared__ int sh[512];
    int v = (threadIdx.x < NBLK) ? g_part[threadIdx.x] : 0;
    sh[threadIdx.x] = v;
    __syncthreads();
#pragma unroll
    for (int d = 1; d < 512; d <<= 1) {
        int t = (threadIdx.x >= d) ? sh[threadIdx.x - d] : 0;
        __syncthreads();
        sh[threadIdx.x] += t;
        __syncthreads();
    }
    if (threadIdx.x < NBLK) g_part[threadIdx.x] = sh[threadIdx.x] - v;  // exclusive
}

// scan_final fused with dis computation (75000-wide grid covers both)
__global__ void scan_final_dis_kernel() {
    int i = blockIdx.x * 256 + threadIdx.x;
    if (i >= NTOT) return;
    int excl = g_off[i] - g_cnt[i] + g_part[blockIdx.x];
    g_off[i] = excl;
    g_cur[i] = excl;
    if (i < N_NODES) g_dis0[i] = rsqrtf((float)g_deg0[i] + 1.0f);
    if (i < NPOOL)   g_dis1[i] = rsqrtf((float)g_deg1[i] + 1.0f);
}

// ---------------- bf16 3-term split GEMM + block-specialized aux work ----------------
// aux_mode: 0 = none, 1 = count (out-degrees + CSR buckets), 2 = fill (CSR payload)
// Blocks with blockIdx.x >= gemm_bx run the aux path (grid-strided over edges).
#define KP 40
#define NP 136
__global__ __launch_bounds__(256, 2) void bf16x3_gemm_kernel(
    const float* __restrict__ A, const float* __restrict__ W,
    const float* __restrict__ bptr, const float* __restrict__ sptr, const float* __restrict__ tptr,
    float* __restrict__ C, int nrows, int K, int M, int act,
    int gemm_bx, int aux_mode,
    const int* __restrict__ ei, const float* __restrict__ ea, const int* __restrict__ cluster,
    const float* __restrict__ We0, const float* __restrict__ be0,
    const float* __restrict__ We1, const float* __restrict__ be1) {
    __shared__ __nv_bfloat16 Ah[128][KP];
    __shared__ __nv_bfloat16 Al[128][KP];
    __shared__ __nv_bfloat16 Bh[32][NP];
    __shared__ __nv_bfloat16 Bl[32][NP];
    int tid = threadIdx.x;

    if ((int)blockIdx.x >= gemm_bx) {
        int ab = blockIdx.x - gemm_bx;          // 0..AUXBLK-1
        if (aux_mode == 1) {
            // count: out-degrees (norm) + in-degree buckets (CSR)
            for (int e = ab * 256 + tid; e < N_EDGES; e += AUXBLK * 256) {
                int r = __ldg(&ei[e]);
                int c = __ldg(&ei[N_EDGES + e]);
                atomicAdd(&g_deg0[r], 1);
                atomicAdd(&g_cnt[c], 1);
                int rp = __ldg(&cluster[r]), cp = __ldg(&cluster[c]);
                if (rp != cp) {
                    atomicAdd(&g_deg1[rp], 1);
                    atomicAdd(&g_cnt[N_NODES + cp], 1);
                }
            }
        } else if (aux_mode == 2) {
            // fill: edge weights + coefficients into CSR buckets
            float* sw = (float*)&Ah[0][0];      // reuse smem corner: [0..11] W0, [12..23] W1, [24] b0, [25] b1
            if (tid < 12) sw[tid] = We0[tid];
            else if (tid < 24) sw[tid] = We1[tid - 12];
            else if (tid == 24) sw[24] = be0[0];
            else if (tid == 25) sw[25] = be1[0];
            __syncthreads();
            for (int e = ab * 256 + tid; e < N_EDGES; e += AUXBLK * 256) {
                const float* a = ea + (size_t)e * 12;
                float w0 = sw[24], w1 = sw[25];
#pragma unroll
                for (int k = 0; k < 12; k++) { float av = __ldg(&a[k]); w0 += av * sw[k]; w1 += av * sw[k + 12]; }
                int r = __ldg(&ei[e]);
                int c = __ldg(&ei[N_EDGES + e]);
                float cf0 = g_dis0[r] * g_dis0[c] * w0;
                int p = atomicAdd(&g_cur[c], 1);
                g_srcA[p] = r;
                g_cfA[p]  = cf0;
                int rp = __ldg(&cluster[r]), cp = __ldg(&cluster[c]);
                if (rp != cp) {
                    float cf1 = g_dis1[rp] * g_dis1[cp] * w1;
                    int q = atomicAdd(&g_cur[N_NODES + cp], 1);
                    g_srcA[q] = rp;
                    g_cfA[q]  = cf1;
                }
            }
        }
        return;
    }

    int row0 = blockIdx.x * 128;
    int col0 = blockIdx.y * 128;
    int wid = tid >> 5, lane = tid & 31;
    int wm = wid & 3;
    int wn = wid >> 2;
    int gid = lane >> 2, tig = lane & 3;
    int sub = lane >> 3, lr = lane & 7;

    uint32_t baseAh = (uint32_t)__cvta_generic_to_shared(&Ah[0][0]);
    uint32_t baseAl = (uint32_t)__cvta_generic_to_shared(&Al[0][0]);
    uint32_t baseBh = (uint32_t)__cvta_generic_to_shared(&Bh[0][0]);
    uint32_t baseBl = (uint32_t)__cvta_generic_to_shared(&Bl[0][0]);
    uint32_t offA = ((wm * 32 + (sub & 1) * 8 + lr) * KP + (sub >> 1) * 8) * 2;
    uint32_t offB = (((sub & 1) * 8 + lr) * NP + wn * 64 + (sub >> 1) * 8) * 2;

    float acc[2][8][4];
#pragma unroll
    for (int i = 0; i < 2; i++)
#pragma unroll
        for (int j = 0; j < 8; j++)
#pragma unroll
            for (int q = 0; q < 4; q++) acc[i][j][q] = 0.f;

    for (int kk = 0; kk < K; kk += 32) {
#pragma unroll
        for (int l = 0; l < 4; l++) {
            int f = tid + l * 256;
            int ar = f >> 3;
            int ak = (f & 7) * 4;
            int grow = row0 + ar;
            float4 v = make_float4(0.f, 0.f, 0.f, 0.f);
            if (grow < nrows) v = *(const float4*)&A[(size_t)grow * K + kk + ak];
            float vv[4] = {v.x, v.y, v.z, v.w};
            __nv_bfloat16 h0 = __float2bfloat16_rn(vv[0]);
            __nv_bfloat16 h1 = __float2bfloat16_rn(vv[1]);
            __nv_bfloat16 h2 = __float2bfloat16_rn(vv[2]);
            __nv_bfloat16 h3 = __float2bfloat16_rn(vv[3]);
            *(__nv_bfloat162*)&Ah[ar][ak]     = __nv_bfloat162(h0, h1);
            *(__nv_bfloat162*)&Ah[ar][ak + 2] = __nv_bfloat162(h2, h3);
            *(__nv_bfloat162*)&Al[ar][ak] = __nv_bfloat162(
                __float2bfloat16_rn(vv[0] - __bfloat162float(h0)),
                __float2bfloat16_rn(vv[1] - __bfloat162float(h1)));
            *(__nv_bfloat162*)&Al[ar][ak + 2] = __nv_bfloat162(
                __float2bfloat16_rn(vv[2] - __bfloat162float(h2)),
                __float2bfloat16_rn(vv[3] - __bfloat162float(h3)));
        }
#pragma unroll
        for (int l = 0; l < 4; l++) {
            int f = tid + l * 256;
            int bk = f >> 5;
            int bn = (f & 31) * 4;
            float4 v = *(const float4*)&W[(size_t)(kk + bk) * M + col0 + bn];
            float vv[4] = {v.x, v.y, v.z, v.w};
            __nv_bfloat16 h0 = __float2bfloat16_rn(vv[0]);
            __nv_bfloat16 h1 = __float2bfloat16_rn(vv[1]);
            __nv_bfloat16 h2 = __float2bfloat16_rn(vv[2]);
            __nv_bfloat16 h3 = __float2bfloat16_rn(vv[3]);
            *(__nv_bfloat162*)&Bh[bk][bn]     = __nv_bfloat162(h0, h1);
            *(__nv_bfloat162*)&Bh[bk][bn + 2] = __nv_bfloat162(h2, h3);
            *(__nv_bfloat162*)&Bl[bk][bn] = __nv_bfloat162(
                __float2bfloat16_rn(vv[0] - __bfloat162float(h0)),
                __float2bfloat16_rn(vv[1] - __bfloat162float(h1)));
            *(__nv_bfloat162*)&Bl[bk][bn + 2] = __nv_bfloat162(
                __float2bfloat16_rn(vv[2] - __bfloat162float(h2)),
                __float2bfloat16_rn(vv[3] - __bfloat162float(h3)));
        }
        __syncthreads();
#pragma unroll
        for (int ks = 0; ks < 2; ks++) {
            uint32_t ah[2][4], al[2][4];
#pragma unroll
            for (int i = 0; i < 2; i++) {
                uint32_t da = offA + (i * 16 * KP + ks * 16) * 2;
                ldsm4(ah[i][0], ah[i][1], ah[i][2], ah[i][3], baseAh + da);
                ldsm4(al[i][0], al[i][1], al[i][2], al[i][3], baseAl + da);
            }
#pragma unroll
            for (int jp = 0; jp < 4; jp++) {
                uint32_t db = offB + (ks * 16 * NP + jp * 16) * 2;
                uint32_t bh[4], bl[4];
                ldsm4t(bh[0], bh[1], bh[2], bh[3], baseBh + db);
                ldsm4t(bl[0], bl[1], bl[2], bl[3], baseBl + db);
#pragma unroll
                for (int jj = 0; jj < 2; jj++) {
                    int j = jp * 2 + jj;
#pragma unroll
                    for (int i = 0; i < 2; i++) {
                        asm volatile(
                            "mma.sync.aligned.m16n8k16.row.col.f32.bf16.bf16.f32 "
                            "{%0,%1,%2,%3},{%4,%5,%6,%7},{%8,%9},{%0,%1,%2,%3};"
                            : "+f"(acc[i][j][0]), "+f"(acc[i][j][1]),
                              "+f"(acc[i][j][2]), "+f"(acc[i][j][3])
                            : "r"(ah[i][0]), "r"(ah[i][1]), "r"(ah[i][2]), "r"(ah[i][3]),
                              "r"(bh[jj * 2]), "r"(bh[jj * 2 + 1]));
                        asm volatile(
                            "mma.sync.aligned.m16n8k16.row.col.f32.bf16.bf16.f32 "
                            "{%0,%1,%2,%3},{%4,%5,%6,%7},{%8,%9},{%0,%1,%2,%3};"
                            : "+f"(acc[i][j][0]), "+f"(acc[i][j][1]),
                              "+f"(acc[i][j][2]), "+f"(acc[i][j][3])
                            : "r"(ah[i][0]), "r"(ah[i][1]), "r"(ah[i][2]), "r"(ah[i][3]),
                              "r"(bl[jj * 2]), "r"(bl[jj * 2 + 1]));
                        asm volatile(
                            "mma.sync.aligned.m16n8k16.row.col.f32.bf16.bf16.f32 "
                            "{%0,%1,%2,%3},{%4,%5,%6,%7},{%8,%9},{%0,%1,%2,%3};"
                            : "+f"(acc[i][j][0]), "+f"(acc[i][j][1]),
                              "+f"(acc[i][j][2]), "+f"(acc[i][j][3])
                            : "r"(al[i][0]), "r"(al[i][1]), "r"(al[i][2]), "r"(al[i][3]),
                              "r"(bh[jj * 2]), "r"(bh[jj * 2 + 1]));
                    }
                }
            }
        }
        __syncthreads();
    }

    int rbase = row0 + wm * 32;
    int cbase = col0 + wn * 64;
#pragma unroll
    for (int j = 0; j < 8; j++) {
        int c0 = cbase + j * 8 + 2 * tig;
        float s0 = 1.f, s1 = 1.f, bb0 = 0.f, bb1 = 0.f;
        if (bptr) { bb0 = bptr[c0]; bb1 = bptr[c0 + 1]; }
        if (sptr) {
            s0 = sptr[c0]; s1 = sptr[c0 + 1];
            bb0 = bb0 * s0 + tptr[c0];
            bb1 = bb1 * s1 + tptr[c0 + 1];
        }
#pragma unroll
        for (int i = 0; i < 2; i++) {
            int r0 = rbase + i * 16 + gid;
#pragma unroll
            for (int h = 0; h < 2; h++) {
                int r = r0 + h * 8;
                if (r < nrows) {
                    float u0 = acc[i][j][h * 2 + 0] * s0 + bb0;
                    float u1 = acc[i][j][h * 2 + 1] * s1 + bb1;
                    if (act) { u0 = leaky(u0); u1 = leaky(u1); }
                    *(float2*)&C[(size_t)r * M + c0] = make_float2(u0, u1);
                }
            }
        }
    }
}

// ---------------- CSR gather body: 4-way unrolled weighted row accumulation ----------------
__device__ __forceinline__ float4 gather_rows(const float* __restrict__ tbl,
                                              int base, int cnt, int lane) {
    float4 a0 = make_float4(0.f, 0.f, 0.f, 0.f);
    float4 a1 = make_float4(0.f, 0.f, 0.f, 0.f);
    float4 a2 = make_float4(0.f, 0.f, 0.f, 0.f);
    float4 a3 = make_float4(0.f, 0.f, 0.f, 0.f);
    int k = 0;
    for (; k + 4 <= cnt; k += 4) {
        int s0 = __ldg(&g_srcA[base + k]);
        int s1 = __ldg(&g_srcA[base + k + 1]);
        int s2 = __ldg(&g_srcA[base + k + 2]);
        int s3 = __ldg(&g_srcA[base + k + 3]);
        float c0 = __ldg(&g_cfA[base + k]);
        float c1 = __ldg(&g_cfA[base + k + 1]);
        float c2 = __ldg(&g_cfA[base + k + 2]);
        float c3 = __ldg(&g_cfA[base + k + 3]);
        float4 v0 = *(const float4*)&tbl[(size_t)s0 * DIM + lane * 4];
        float4 v1 = *(const float4*)&tbl[(size_t)s1 * DIM + lane * 4];
        float4 v2 = *(const float4*)&tbl[(size_t)s2 * DIM + lane * 4];
        float4 v3 = *(const float4*)&tbl[(size_t)s3 * DIM + lane * 4];
        a0.x += c0 * v0.x; a0.y += c0 * v0.y; a0.z += c0 * v0.z; a0.w += c0 * v0.w;
        a1.x += c1 * v1.x; a1.y += c1 * v1.y; a1.z += c1 * v1.z; a1.w += c1 * v1.w;
        a2.x += c2 * v2.x; a2.y += c2 * v2.y; a2.z += c2 * v2.z; a2.w += c2 * v2.w;
        a3.x += c3 * v3.x; a3.y += c3 * v3.y; a3.z += c3 * v3.z; a3.w += c3 * v3.w;
    }
    for (; k < cnt; k++) {
        int s0 = __ldg(&g_srcA[base + k]);
        float c0 = __ldg(&g_cfA[base + k]);
        float4 v0 = *(const float4*)&tbl[(size_t)s0 * DIM + lane * 4];
        a0.x += c0 * v0.x; a0.y += c0 * v0.y; a0.z += c0 * v0.z; a0.w += c0 * v0.w;
    }
    a0.x += a1.x + a2.x + a3.x;
    a0.y += a1.y + a2.y + a3.y;
    a0.z += a1.z + a2.z + a3.z;
    a0.w += a1.w + a2.w + a3.w;
    return a0;
}

// ---------------- gather layer0 + post + graclus pool (warp per pooled node) ----------------
__global__ __launch_bounds__(256) void gather0_pool_kernel(const float* __restrict__ origin,
                                                           const float* __restrict__ We,
                                                           const float* __restrict__ be) {
    __shared__ float swself;
    if (threadIdx.x == 0) {
        float t = be[0];
        for (int k = 0; k < 12; k++) t += We[k];
        swself = t;
    }
    __syncthreads();
    int j = blockIdx.x * 8 + (threadIdx.x >> 5);
    if (j >= NPOOL) return;
    int lane = threadIdx.x & 31;
    float4 vmax;
#pragma unroll
    for (int t = 0; t < 2; t++) {
        int n = 2 * j + t;
        float4 a = gather_rows(g_h0, g_off[n], g_cnt[n], lane);
        float ds = g_dis0[n];
        float sc = ds * ds * swself;
        float4 h  = *(const float4*)&g_h0[(size_t)n * DIM + lane * 4];
        float4 og = *(const float4*)&origin[(size_t)n * DIM + lane * 4];
        float4 v;
        v.x = leaky(a.x + sc * h.x + og.x);
        v.y = leaky(a.y + sc * h.y + og.y);
        v.z = leaky(a.z + sc * h.z + og.z);
        v.w = leaky(a.w + sc * h.w + og.w);
        if (t == 0) vmax = v;
        else {
            vmax.x = fmaxf(vmax.x, v.x); vmax.y = fmaxf(vmax.y, v.y);
            vmax.z = fmaxf(vmax.z, v.z); vmax.w = fmaxf(vmax.w, v.w);
        }
    }
    *(float4*)&g_xp[(size_t)j * DIM + lane * 4] = vmax;
}

// ---------------- gather layer1 + post + global max pool (warp per pooled node) ----------------
__global__ __launch_bounds__(256) void gather1_gmax_kernel(const int* __restrict__ batch_p,
                                                           const float* __restrict__ We,
                                                           const float* __restrict__ be) {
    __shared__ float swself;
    if (threadIdx.x == 0) {
        float t = be[0];
        for (int k = 0; k < 12; k++) t += We[k];
        swself = t;
    }
    __syncthreads();
    int j = blockIdx.x * 8 + (threadIdx.x >> 5);
    if (j >= NPOOL) return;
    int lane = threadIdx.x & 31;
    float4 a = gather_rows(g_h1m, g_off[N_NODES + j], g_cnt[N_NODES + j], lane);
    float ds = g_dis1[j];
    float sc = ds * ds * swself;
    float4 hm = *(const float4*)&g_h1m[(size_t)j * DIM + lane * 4];
    float v0 = leaky(a.x + sc * hm.x);
    float v1 = leaky(a.y + sc * hm.y);
    float v2 = leaky(a.z + sc * hm.z);
    float v3 = leaky(a.w + sc * hm.w);
    int b = __ldg(&batch_p[j]);
    unsigned* gp = &g_gmax[b * DIM + lane * 4];
    atomicMax(&gp[0], encf(v0)); atomicMax(&gp[1], encf(v1));
    atomicMax(&gp[2], encf(v2)); atomicMax(&gp[3], encf(v3));
}

// ---------------- head MLP: [G,128] -> [G,64] -> [G,1] ----------------
__global__ void head_kernel(const float* __restrict__ W1, const float* __restrict__ b1,
                            const float* __restrict__ s, const float* __restrict__ t,
                            const float* __restrict__ W2, const float* __restrict__ b2,
                            float* __restrict__ out) {
    __shared__ float grow[128];
    __shared__ float red[64];
    int r = blockIdx.x;
    int h = threadIdx.x;
    grow[h]      = decf(g_gmax[r * DIM + h]);
    grow[h + 64] = decf(g_gmax[r * DIM + h + 64]);
    __syncthreads();
    float acc = 0.f;
#pragma unroll 4
    for (int k = 0; k < 128; k++) acc += grow[k] * W1[k * 64 + h];
    float v = (acc + b1[h]) * s[h] + t[h];
    v = leaky(v);
    red[h] = v * W2[h];
    __syncthreads();
    if (h == 0) {
        float total = b2[0];
        for (int k = 0; k < 64; k++) total += red[k];
        out[r] = total;
    }
}

// ---------------- launch ----------------
extern "C" void kernel_launch(void* const* d_in, const int* in_sizes, int n_in,
                              void* d_out, int out_size) {
    const float* x = (const float*)d_in[0];
    const float* origin;
    const float* ea;
    const int* ei;
    if (in_sizes[1] == N_NODES * DIM) {
        origin = (const float*)d_in[1];
        ea     = (const float*)d_in[2];
        ei     = (const int*)d_in[3];
    } else {
        ei     = (const int*)d_in[1];
        ea     = (const float*)d_in[2];
        origin = (const float*)d_in[3];
    }
    const int* cluster = (const int*)d_in[4];
    const int* batch_p = (const int*)d_in[5];
    const float* l0_W1 = (const float*)d_in[6];
    const float* l0_b1 = (const float*)d_in[7];
    const float* l0_s  = (const float*)d_in[8];
    const float* l0_t  = (const float*)d_in[9];
    const float* l0_W2 = (const float*)d_in[10];
    const float* l0_b2 = (const float*)d_in[11];
    const float* l0_We = (const float*)d_in[12];
    const float* l0_be = (const float*)d_in[13];
    const float* l1_W1 = (const float*)d_in[14];
    const float* l1_b1 = (const float*)d_in[15];
    const float* l1_s  = (const float*)d_in[16];
    const float* l1_t  = (const float*)d_in[17];
    const float* l1_W2 = (const float*)d_in[18];
    const float* l1_b2 = (const float*)d_in[19];
    const float* l1_We = (const float*)d_in[20];
    const float* l1_be = (const float*)d_in[21];
    const float* hd_W1 = (const float*)d_in[22];
    const float* hd_b1 = (const float*)d_in[23];
    const float* hd_s  = (const float*)d_in[24];
    const float* hd_t  = (const float*)d_in[25];
    const float* hd_W2 = (const float*)d_in[26];
    const float* hd_b2 = (const float*)d_in[27];
    float* out = (float*)d_out;

    float *p_h0, *p_t1, *p_xp, *p_h1m;
    cudaGetSymbolAddress((void**)&p_h0,  g_h0);
    cudaGetSymbolAddress((void**)&p_t1,  g_t1);
    cudaGetSymbolAddress((void**)&p_xp,  g_xp);
    cudaGetSymbolAddress((void**)&p_h1m, g_h1m);

    const int GB0 = (N_NODES + 127) / 128;   // 391
    const int GB1 = (NPOOL + 127) / 128;     // 196

    zero_kernel<<<256, 256>>>();

    // GEMM0 (t1 = leaky((x@W1)*s + bias)) + count aux blocks
    bf16x3_gemm_kernel<<<dim3(GB0 + AUXBLK, 1), 256>>>(
        x, l0_W1, l0_b1, l0_s, l0_t, p_t1, N_NODES, 128, 128, 1,
        GB0, 1, ei, ea, cluster, l0_We, l0_be, l1_We, l1_be);

    scan_part_kernel<<<NBLK, 256>>>();
    scan_part2_kernel<<<1, 512>>>();
    scan_final_dis_kernel<<<NBLK, 256>>>();

    // GEMM1 (h0 = t1@W2 + b2) + fill aux blocks
    bf16x3_gemm_kernel<<<dim3(GB0 + AUXBLK, 1), 256>>>(
        p_t1, l0_W2, l0_b2, nullptr, nullptr, p_h0, N_NODES, 128, 128, 0,
        GB0, 2, ei, ea, cluster, l0_We, l0_be, l1_We, l1_be);

    gather0_pool_kernel<<<(NPOOL + 7) / 8, 256>>>(origin, l0_We, l0_be);

    // MLP1: t1 = leaky((xp@W1)*s + bias) [NPOOL,256];  h1m = t1@W2 + b2
    bf16x3_gemm_kernel<<<dim3(GB1, 2), 256>>>(
        p_xp, l1_W1, l1_b1, l1_s, l1_t, p_t1, NPOOL, 128, 256, 1,
        GB1, 0, ei, ea, cluster, l1_We, l1_be, l1_We, l1_be);
    bf16x3_gemm_kernel<<<dim3(GB1, 1), 256>>>(
        p_t1, l1_W2, l1_b2, nullptr, nullptr, p_h1m, NPOOL, 256, 128, 0,
        GB1, 0, ei, ea, cluster, l1_We, l1_be, l1_We, l1_be);

    gather1_gmax_kernel<<<(NPOOL + 7) / 8, 256>>>(batch_p, l1_We, l1_be);
    head_kernel<<<NGRAPH, 64>>>(hd_W1, hd_b1, hd_s, hd_t, hd_W2, hd_b2, out);
}